// round 15
// baseline (speedup 1.0000x reference)
#include <cuda_runtime.h>
#include <cuda_fp16.h>
#include <math.h>
#include <float.h>

// Problem constants
#define B_    8
#define T_    512
#define IDIM  1799
#define D_    256
#define H_    4
#define FF_   2048
#define L_    16
#define DK    64
#define BT    (B_*T_)    // 4096
#define BH    (B_*H_)    // 32
#define NPK   1023       // distinct rel-pos rows: t-s+511 in [0,1022]

// ------------------------- scratch (device globals) -------------------------
__device__ float g_x[BT*D_];
__device__ float g_y[BT*D_];
__device__ float g_v[BT*D_];
__device__ float g_mu[BT];
__device__ float g_rs[BT];
__device__ __half g_oh[BT*D_];
__device__ __half g_qh[BT*D_];
__device__ __half g_kh[BT*D_];
__device__ __half g_ffh[(size_t)BT*FF_];
__device__ __half g_pkn[(size_t)L_*NPK*DK];
// fp16 weights
__device__ __half g_hemb[D_*IDIM];
__device__ __half g_hq[(size_t)L_*D_*D_];
__device__ __half g_hk[(size_t)L_*D_*D_];
__device__ __half g_hv[(size_t)L_*D_*D_];
__device__ __half g_ho[(size_t)L_*D_*D_];
__device__ __half g_h1[(size_t)L_*FF_*D_];
__device__ __half g_h2[(size_t)L_*D_*FF_];

// ------------------------- helpers -------------------------
__device__ __forceinline__ unsigned f2tf(float f) {
    unsigned r;
    asm("cvt.rna.tf32.f32 %0, %1;" : "=r"(r) : "f"(f));
    return r;
}
__device__ __forceinline__ unsigned pack_h2(float lo, float hi) {
    unsigned u;
    asm("cvt.rn.f16x2.f32 %0, %1, %2;" : "=r"(u) : "f"(hi), "f"(lo));
    return u;
}
__device__ __forceinline__ unsigned sptr(const void* p) {
    return (unsigned)__cvta_generic_to_shared(p);
}
__device__ __forceinline__ void ldsm4(unsigned& r0, unsigned& r1, unsigned& r2, unsigned& r3,
                                      unsigned addr) {
    asm volatile("ldmatrix.sync.aligned.m8n8.x4.shared.b16 {%0,%1,%2,%3}, [%4];"
                 : "=r"(r0), "=r"(r1), "=r"(r2), "=r"(r3) : "r"(addr));
}
__device__ __forceinline__ void mma_tf32(float c[4],
                                         unsigned a0, unsigned a1, unsigned a2, unsigned a3,
                                         unsigned b0, unsigned b1) {
    asm volatile(
        "mma.sync.aligned.m16n8k8.row.col.f32.tf32.tf32.f32 "
        "{%0,%1,%2,%3}, {%4,%5,%6,%7}, {%8,%9}, {%0,%1,%2,%3};"
        : "+f"(c[0]), "+f"(c[1]), "+f"(c[2]), "+f"(c[3])
        : "r"(a0), "r"(a1), "r"(a2), "r"(a3), "r"(b0), "r"(b1));
}
__device__ __forceinline__ void mma_f16(float c[4],
                                        unsigned a0, unsigned a1, unsigned a2, unsigned a3,
                                        unsigned b0, unsigned b1) {
    asm volatile(
        "mma.sync.aligned.m16n8k16.row.col.f32.f16.f16.f32 "
        "{%0,%1,%2,%3}, {%4,%5,%6,%7}, {%8,%9}, {%0,%1,%2,%3};"
        : "+f"(c[0]), "+f"(c[1]), "+f"(c[2]), "+f"(c[3])
        : "r"(a0), "r"(a1), "r"(a2), "r"(a3), "r"(b0), "r"(b1));
}

// ------------------------- fp32 -> fp16 bulk convert -------------------------
__global__ __launch_bounds__(256) void f2h(const float* __restrict__ in,
                                           __half* __restrict__ out, int n4) {
    int i = blockIdx.x * 256 + threadIdx.x;
    if (i < n4) {
        float4 v = *(const float4*)&in[i * 4];
        uint2 o;
        o.x = pack_h2(v.x, v.y);
        o.y = pack_h2(v.z, v.w);
        *(uint2*)&out[i * 4] = o;
    }
}

// ------------------------- block reduction (for pkn LN only) -------------------------
__device__ __forceinline__ float block_sum64(float v) {
    __shared__ float sh[3];
    #pragma unroll
    for (int o = 16; o > 0; o >>= 1) v += __shfl_xor_sync(0xffffffffu, v, o);
    int lane = threadIdx.x & 31, w = threadIdx.x >> 5;
    if (lane == 0) sh[w] = v;
    __syncthreads();
    float out = sh[0] + sh[1];
    __syncthreads();
    return out;
}

// all-layers pkn LN -> fp16: grid (NPK, L), block 64
__global__ void ln_pkn_all(const float* __restrict__ pe_k, __half* __restrict__ pkn,
                           const float* __restrict__ lnk_g, const float* __restrict__ lnk_b) {
    int row = blockIdx.x, l = blockIdx.y;
    float x = pe_k[(size_t)(489 + row) * DK + threadIdx.x];
    float mean = block_sum64(x) / (float)DK;
    float d = x - mean;
    float var = block_sum64(d * d) / (float)DK;
    float y = d * rsqrtf(var + 1e-12f) * lnk_g[l * DK + threadIdx.x] + lnk_b[l * DK + threadIdx.x];
    pkn[((size_t)l * NPK + row) * DK + threadIdx.x] = __float2half_rn(y);
}

// ------------------------- warp-per-row LayerNorm, width 256 -------------------------
__global__ __launch_bounds__(256) void ln_warp(const float* __restrict__ in,
                                               float* __restrict__ out,
                                               const float* __restrict__ g,
                                               const float* __restrict__ bb,
                                               int relu) {
    int warp = threadIdx.x >> 5, lane = threadIdx.x & 31;
    size_t row = (size_t)blockIdx.x * 8 + warp;
    const float* ip = in + row * D_;
    float4 v0 = *(const float4*)&ip[lane * 4];
    float4 v1 = *(const float4*)&ip[128 + lane * 4];
    float s = v0.x + v0.y + v0.z + v0.w + v1.x + v1.y + v1.z + v1.w;
    #pragma unroll
    for (int o = 16; o > 0; o >>= 1) s += __shfl_xor_sync(0xffffffffu, s, o);
    float mean = s * (1.0f / 256.0f);
    float d0x = v0.x - mean, d0y = v0.y - mean, d0z = v0.z - mean, d0w = v0.w - mean;
    float d1x = v1.x - mean, d1y = v1.y - mean, d1z = v1.z - mean, d1w = v1.w - mean;
    float vs = d0x*d0x + d0y*d0y + d0z*d0z + d0w*d0w + d1x*d1x + d1y*d1y + d1z*d1z + d1w*d1w;
    #pragma unroll
    for (int o = 16; o > 0; o >>= 1) vs += __shfl_xor_sync(0xffffffffu, vs, o);
    float rstd = rsqrtf(vs * (1.0f / 256.0f) + 1e-12f);
    float4 g0 = *(const float4*)&g[lane * 4];
    float4 g1 = *(const float4*)&g[128 + lane * 4];
    float4 b0 = *(const float4*)&bb[lane * 4];
    float4 b1 = *(const float4*)&bb[128 + lane * 4];
    float4 o0, o1;
    o0.x = d0x * rstd * g0.x + b0.x;  o0.y = d0y * rstd * g0.y + b0.y;
    o0.z = d0z * rstd * g0.z + b0.z;  o0.w = d0w * rstd * g0.w + b0.w;
    o1.x = d1x * rstd * g1.x + b1.x;  o1.y = d1y * rstd * g1.y + b1.y;
    o1.z = d1z * rstd * g1.z + b1.z;  o1.w = d1w * rstd * g1.w + b1.w;
    if (relu) {
        o0.x = fmaxf(o0.x, 0.f); o0.y = fmaxf(o0.y, 0.f); o0.z = fmaxf(o0.z, 0.f); o0.w = fmaxf(o0.w, 0.f);
        o1.x = fmaxf(o1.x, 0.f); o1.y = fmaxf(o1.y, 0.f); o1.z = fmaxf(o1.z, 0.f); o1.w = fmaxf(o1.w, 0.f);
    }
    float* op = out + row * D_;
    *(float4*)&op[lane * 4] = o0;
    *(float4*)&op[128 + lane * 4] = o1;
}

// ------------------------- warp-per-row LN stats (mean, rstd) -------------------------
__global__ __launch_bounds__(256) void ln_stats(const float* __restrict__ in,
                                                float* __restrict__ mu,
                                                float* __restrict__ rs) {
    int warp = threadIdx.x >> 5, lane = threadIdx.x & 31;
    size_t row = (size_t)blockIdx.x * 8 + warp;
    const float* ip = in + row * D_;
    float4 v0 = *(const float4*)&ip[lane * 4];
    float4 v1 = *(const float4*)&ip[128 + lane * 4];
    float s = v0.x + v0.y + v0.z + v0.w + v1.x + v1.y + v1.z + v1.w;
    #pragma unroll
    for (int o = 16; o > 0; o >>= 1) s += __shfl_xor_sync(0xffffffffu, s, o);
    float mean = s * (1.0f / 256.0f);
    float d0x = v0.x - mean, d0y = v0.y - mean, d0z = v0.z - mean, d0w = v0.w - mean;
    float d1x = v1.x - mean, d1y = v1.y - mean, d1z = v1.z - mean, d1w = v1.w - mean;
    float vs = d0x*d0x + d0y*d0y + d0z*d0z + d0w*d0w + d1x*d1x + d1y*d1y + d1z*d1z + d1w*d1w;
    #pragma unroll
    for (int o = 16; o > 0; o >>= 1) vs += __shfl_xor_sync(0xffffffffu, vs, o);
    if (lane == 0) {
        mu[row] = mean;
        rs[row] = rsqrtf(vs * (1.0f / 256.0f) + 1e-12f);
    }
}

// ------------------------- FP16 GEMM body, BM=128 BN=64 BK=32 -------------------------
// B always fp16. A fp32 (+opt LN) or fp16 (template AH). C fp32 (+opt residual) or fp16.
// Fragment loads via ldmatrix.x4.
#define STRH 20
template<bool AH>
__device__ __forceinline__ void tg128_body(
    const void* __restrict__ Ap, const __half* __restrict__ Bm,
    const float* __restrict__ bias, const float* __restrict__ R,
    void* __restrict__ Cp, int N, int K, int mode, int c_half, int r0, int c0,
    const float* __restrict__ mu, const float* __restrict__ rs,
    const float* __restrict__ lg, const float* __restrict__ lb)
{
    __shared__ unsigned As[128 * STRH];
    __shared__ unsigned Bs[64 * STRH];

    int tid = threadIdx.x;
    int lane = tid & 31, warp = tid >> 5;
    int wm = warp >> 1, wn = warp & 1;
    int g = lane >> 2, tg = lane & 3;

    // ldmatrix lane-address components
    int rA  = ((lane >> 3) & 1) * 8 + (lane & 7);   // A row within 16
    int kAw = ((lane >> 4) & 1) * 4;                // A k-half (words)
    int cBr = lane & 7;                             // B col within 8
    int cBs = ((lane >> 4) & 1);                    // B nt-within-pair
    int kBw = ((lane >> 3) & 1) * 4;                // B k-half (words)

    const float*  Af = AH ? nullptr : (const float*)Ap + (size_t)r0 * K;
    const __half* Ah = AH ? (const __half*)Ap + (size_t)r0 * K : nullptr;
    const __half* Bb = Bm + (size_t)c0 * K;

    float acc[2][4][4];
    #pragma unroll
    for (int mt = 0; mt < 2; mt++)
        #pragma unroll
        for (int nt = 0; nt < 4; nt++)
            #pragma unroll
            for (int e = 0; e < 4; e++) acc[mt][nt][e] = 0.0f;

    float muv[4], rsv[4];
    if (!AH && lg) {
        #pragma unroll
        for (int i = 0; i < 4; i++) {
            int r = (tid + i * 256) >> 3;
            muv[i] = mu[r0 + r];
            rsv[i] = rs[r0 + r];
        }
    }

    auto do_mma = [&]() {
        #pragma unroll
        for (int kc = 0; kc < 2; kc++) {
            int ko = kc * 8;
            unsigned a[2][4], b[4][2];
            #pragma unroll
            for (int mt = 0; mt < 2; mt++) {
                int row = wm * 32 + mt * 16 + rA;
                ldsm4(a[mt][0], a[mt][1], a[mt][2], a[mt][3],
                      sptr(&As[row * STRH + ko + kAw]));
            }
            #pragma unroll
            for (int np = 0; np < 2; np++) {
                int col = wn * 32 + (np * 2 + cBs) * 8 + cBr;
                unsigned q0, q1, q2, q3;
                ldsm4(q0, q1, q2, q3, sptr(&Bs[col * STRH + ko + kBw]));
                b[np * 2][0] = q0; b[np * 2][1] = q1;
                b[np * 2 + 1][0] = q2; b[np * 2 + 1][1] = q3;
            }
            #pragma unroll
            for (int mt = 0; mt < 2; mt++)
                #pragma unroll
                for (int nt = 0; nt < 4; nt++)
                    mma_f16(acc[mt][nt], a[mt][0], a[mt][1], a[mt][2], a[mt][3],
                            b[nt][0], b[nt][1]);
        }
    };

    if ((K & 31) == 0) {
        int nch = K >> 5;
        int br = tid >> 2, bc8 = tid & 3;
        uint4 pbh = *(const uint4*)&Bb[(size_t)br * K + bc8 * 8];

        if (AH) {
            uint4 pah[2];
            #pragma unroll
            for (int i = 0; i < 2; i++) {
                int idx = tid + i * 256, r = idx >> 2, c8 = idx & 3;
                pah[i] = *(const uint4*)&Ah[(size_t)r * K + c8 * 8];
            }
            #pragma unroll
            for (int i = 0; i < 2; i++) {
                int idx = tid + i * 256, r = idx >> 2, c8 = idx & 3;
                *(uint4*)&As[r * STRH + c8 * 4] = pah[i];
            }
            *(uint4*)&Bs[br * STRH + bc8 * 4] = pbh;
            __syncthreads();
            for (int ch = 0; ch < nch; ch++) {
                bool more = (ch + 1 < nch);
                int k1 = (ch + 1) << 5;
                if (more) {
                    #pragma unroll
                    for (int i = 0; i < 2; i++) {
                        int idx = tid + i * 256, r = idx >> 2, c8 = idx & 3;
                        pah[i] = *(const uint4*)&Ah[(size_t)r * K + k1 + c8 * 8];
                    }
                    pbh = *(const uint4*)&Bb[(size_t)br * K + k1 + bc8 * 8];
                }
                do_mma();
                if (more) {
                    __syncthreads();
                    #pragma unroll
                    for (int i = 0; i < 2; i++) {
                        int idx = tid + i * 256, r = idx >> 2, c8 = idx & 3;
                        *(uint4*)&As[r * STRH + c8 * 4] = pah[i];
                    }
                    *(uint4*)&Bs[br * STRH + bc8 * 4] = pbh;
                    __syncthreads();
                }
            }
        } else {
            float4 pa[4];
            #pragma unroll
            for (int i = 0; i < 4; i++) {
                int idx = tid + i * 256, r = idx >> 3, c4 = idx & 7;
                pa[i] = *(const float4*)&Af[(size_t)r * K + c4 * 4];
            }
            auto store_a = [&](float4 av, int i, int kbase) {
                int idx = tid + i * 256, r = idx >> 3, c4 = idx & 7;
                if (lg) {
                    float4 ga = *(const float4*)&lg[kbase + c4 * 4];
                    float4 be = *(const float4*)&lb[kbase + c4 * 4];
                    float m = muv[i], rr = rsv[i];
                    av.x = (av.x - m) * rr * ga.x + be.x;
                    av.y = (av.y - m) * rr * ga.y + be.y;
                    av.z = (av.z - m) * rr * ga.z + be.z;
                    av.w = (av.w - m) * rr * ga.w + be.w;
                }
                unsigned* ap = &As[r * STRH + c4 * 2];
                ap[0] = pack_h2(av.x, av.y);
                ap[1] = pack_h2(av.z, av.w);
            };
            #pragma unroll
            for (int i = 0; i < 4; i++) store_a(pa[i], i, 0);
            *(uint4*)&Bs[br * STRH + bc8 * 4] = pbh;
            __syncthreads();
            for (int ch = 0; ch < nch; ch++) {
                bool more = (ch + 1 < nch);
                int k1 = (ch + 1) << 5;
                if (more) {
                    #pragma unroll
                    for (int i = 0; i < 4; i++) {
                        int idx = tid + i * 256, r = idx >> 3, c4 = idx & 7;
                        pa[i] = *(const float4*)&Af[(size_t)r * K + k1 + c4 * 4];
                    }
                    pbh = *(const uint4*)&Bb[(size_t)br * K + k1 + bc8 * 8];
                }
                do_mma();
                if (more) {
                    __syncthreads();
                    #pragma unroll
                    for (int i = 0; i < 4; i++) store_a(pa[i], i, k1);
                    *(uint4*)&Bs[br * STRH + bc8 * 4] = pbh;
                    __syncthreads();
                }
            }
        }
    } else {
        // guarded scalar path (embed GEMM, K=1799): A fp32, B fp16
        for (int k0 = 0; k0 < K; k0 += 32) {
            #pragma unroll
            for (int i = 0; i < 8; i++) {
                int idx = tid + i * 256, r = idx >> 4, c2 = idx & 15;
                int kk = k0 + c2 * 2;
                float f0 = (kk < K)     ? Af[(size_t)r * K + kk]     : 0.0f;
                float f1 = (kk + 1 < K) ? Af[(size_t)r * K + kk + 1] : 0.0f;
                As[r * STRH + c2] = pack_h2(f0, f1);
            }
            #pragma unroll
            for (int i = 0; i < 4; i++) {
                int idx = tid + i * 256, r = idx >> 4, c2 = idx & 15;
                int kk = k0 + c2 * 2;
                float f0 = (kk < K)     ? __half2float(Bb[(size_t)r * K + kk])     : 0.0f;
                float f1 = (kk + 1 < K) ? __half2float(Bb[(size_t)r * K + kk + 1]) : 0.0f;
                Bs[r * STRH + c2] = pack_h2(f0, f1);
            }
            __syncthreads();
            do_mma();
            __syncthreads();
        }
    }

    #pragma unroll
    for (int mt = 0; mt < 2; mt++) {
        int row = r0 + wm * 32 + mt * 16 + g;
        #pragma unroll
        for (int nt = 0; nt < 4; nt++) {
            int col = c0 + wn * 32 + nt * 8 + 2 * tg;
            float2 bi = *(const float2*)&bias[col];
            #pragma unroll
            for (int half = 0; half < 2; half++) {
                int rr = row + half * 8;
                float x0 = acc[mt][nt][half * 2 + 0] + bi.x;
                float x1 = acc[mt][nt][half * 2 + 1] + bi.y;
                if (mode & 2) {
                    float2 rv = *(const float2*)&R[(size_t)rr * N + col];
                    x0 += rv.x; x1 += rv.y;
                }
                if (mode & 1) { x0 = fmaxf(x0, 0.0f); x1 = fmaxf(x1, 0.0f); }
                if (c_half) {
                    *(unsigned*)&((__half*)Cp)[(size_t)rr * N + col] = pack_h2(x0, x1);
                } else {
                    float2 o2 = {x0, x1};
                    *(float2*)&((float*)Cp)[(size_t)rr * N + col] = o2;
                }
            }
        }
    }
}

__global__ __launch_bounds__(256) void tgemm128_f(
    const float* __restrict__ A, const __half* __restrict__ Bm,
    const float* __restrict__ bias, const float* __restrict__ R,
    float* __restrict__ C, int N, int K, int mode)
{
    tg128_body<false>(A, Bm, bias, R, C, N, K, mode, 0,
                      blockIdx.y * 128, blockIdx.x * 64,
                      nullptr, nullptr, nullptr, nullptr);
}

__global__ __launch_bounds__(256) void tgemm128_h(
    const __half* __restrict__ A, const __half* __restrict__ Bm,
    const float* __restrict__ bias, const float* __restrict__ R,
    float* __restrict__ C, int N, int K, int mode)
{
    tg128_body<true>(A, Bm, bias, R, C, N, K, mode, 0,
                     blockIdx.y * 128, blockIdx.x * 64,
                     nullptr, nullptr, nullptr, nullptr);
}

// batched Q/K/V: z=0 -> q (fp16 out), z=1 -> k (fp16 out), z=2 -> v (fp32 out)
__global__ __launch_bounds__(256) void tgemm128_qkv(
    const float* __restrict__ A,
    const __half* __restrict__ Wq, const __half* __restrict__ Wk, const __half* __restrict__ Wv,
    const float* __restrict__ bq, const float* __restrict__ bk, const float* __restrict__ bv,
    __half* __restrict__ qh, __half* __restrict__ kh, float* __restrict__ v,
    const float* __restrict__ mu, const float* __restrict__ rs,
    const float* __restrict__ lg, const float* __restrict__ lb)
{
    const __half* W; const float* bi; void* C; int ch;
    if (blockIdx.z == 0)      { W = Wq; bi = bq; C = qh; ch = 1; }
    else if (blockIdx.z == 1) { W = Wk; bi = bk; C = kh; ch = 1; }
    else                      { W = Wv; bi = bv; C = v;  ch = 0; }
    tg128_body<false>(A, W, bi, nullptr, C, D_, D_, 0, ch,
                      blockIdx.y * 128, blockIdx.x * 64, mu, rs, lg, lb);
}

// ------------------------- FP16 GEMM, BM=128 BN=128 BK=32 (FF1, fp16 out) -----------------
__global__ __launch_bounds__(256) void tgemm256(
    const float* __restrict__ A, const __half* __restrict__ Bm,
    const float* __restrict__ bias, __half* __restrict__ C,
    int N, int K, int mode,
    const float* __restrict__ mu, const float* __restrict__ rs,
    const float* __restrict__ lg, const float* __restrict__ lb)
{
    __shared__ unsigned As[128 * STRH];
    __shared__ unsigned Bs[128 * STRH];

    int tid = threadIdx.x;
    int lane = tid & 31, warp = tid >> 5;
    int wm = warp >> 2, wn = warp & 3;
    int g = lane >> 2, tg = lane & 3;

    int rA  = ((lane >> 3) & 1) * 8 + (lane & 7);
    int kAw = ((lane >> 4) & 1) * 4;
    int cBr = lane & 7;
    int cBs = ((lane >> 4) & 1);
    int kBw = ((lane >> 3) & 1) * 4;

    int r0 = blockIdx.y * 128, c0 = blockIdx.x * 128;
    const float* Ab = A + (size_t)r0 * K;
    const __half* Bb = Bm + (size_t)c0 * K;

    float acc[4][4][4];
    #pragma unroll
    for (int mt = 0; mt < 4; mt++)
        #pragma unroll
        for (int nt = 0; nt < 4; nt++)
            #pragma unroll
            for (int e = 0; e < 4; e++) acc[mt][nt][e] = 0.0f;

    float muv[4], rsv[4];
    if (lg) {
        #pragma unroll
        for (int i = 0; i < 4; i++) {
            int r = (tid + i * 256) >> 3;
            muv[i] = mu[r0 + r];
            rsv[i] = rs[r0 + r];
        }
    }

    for (int k0 = 0; k0 < K; k0 += 32) {
        #pragma unroll
        for (int i = 0; i < 4; i++) {
            int idx = tid + i * 256, r = idx >> 3, c4 = idx & 7;
            float4 av = *(const float4*)&Ab[(size_t)r * K + k0 + c4 * 4];
            if (lg) {
                float4 ga = *(const float4*)&lg[k0 + c4 * 4];
                float4 be = *(const float4*)&lb[k0 + c4 * 4];
                float m = muv[i], rr = rsv[i];
                av.x = (av.x - m) * rr * ga.x + be.x;
                av.y = (av.y - m) * rr * ga.y + be.y;
                av.z = (av.z - m) * rr * ga.z + be.z;
                av.w = (av.w - m) * rr * ga.w + be.w;
            }
            unsigned* ap = &As[r * STRH + c4 * 2];
            ap[0] = pack_h2(av.x, av.y);
            ap[1] = pack_h2(av.z, av.w);
        }
        #pragma unroll
        for (int i = 0; i < 2; i++) {
            int idx = tid + i * 256, r = idx >> 2, c8 = idx & 3;
            uint4 bw = *(const uint4*)&Bb[(size_t)r * K + k0 + c8 * 8];
            *(uint4*)&Bs[r * STRH + c8 * 4] = bw;
        }
        __syncthreads();

        #pragma unroll
        for (int kc = 0; kc < 2; kc++) {
            int ko = kc * 8;
            unsigned a[4][4], b[4][2];
            #pragma unroll
            for (int mt = 0; mt < 4; mt++) {
                int row = wm * 64 + mt * 16 + rA;
                ldsm4(a[mt][0], a[mt][1], a[mt][2], a[mt][3],
                      sptr(&As[row * STRH + ko + kAw]));
            }
            #pragma unroll
            for (int np = 0; np < 2; np++) {
                int col = wn * 32 + (np * 2 + cBs) * 8 + cBr;
                unsigned q0, q1, q2, q3;
                ldsm4(q0, q1, q2, q3, sptr(&Bs[col * STRH + ko + kBw]));
                b[np * 2][0] = q0; b[np * 2][1] = q1;
                b[np * 2 + 1][0] = q2; b[np * 2 + 1][1] = q3;
            }
            #pragma unroll
            for (int mt = 0; mt < 4; mt++)
                #pragma unroll
                for (int nt = 0; nt < 4; nt++)
                    mma_f16(acc[mt][nt], a[mt][0], a[mt][1], a[mt][2], a[mt][3],
                            b[nt][0], b[nt][1]);
        }
        __syncthreads();
    }

    #pragma unroll
    for (int mt = 0; mt < 4; mt++) {
        int row = r0 + wm * 64 + mt * 16 + g;
        #pragma unroll
        for (int nt = 0; nt < 4; nt++) {
            int col = c0 + wn * 32 + nt * 8 + 2 * tg;
            float2 bi = *(const float2*)&bias[col];
            #pragma unroll
            for (int half = 0; half < 2; half++) {
                int rr = row + half * 8;
                float x0 = acc[mt][nt][half * 2 + 0] + bi.x;
                float x1 = acc[mt][nt][half * 2 + 1] + bi.y;
                if (mode & 1) { x0 = fmaxf(x0, 0.0f); x1 = fmaxf(x1, 0.0f); }
                *(unsigned*)&C[(size_t)rr * N + col] = pack_h2(x0, x1);
            }
        }
    }
}

// ------------------------- fully fused flash attention -------------------------
// S/R MMAs fp16 via ldmatrix; P.V tf32. O written fp16.
// DYNAMIC smem (54784 B): Vs[0,18944) Kh[18944,28160) Ph[28160,46592)
//                         Rs/Ru alias [18944,52736)  msk[52736,54784)
#define KSTRH 36
#define VSTR 37
#define VPANE 2368
#define FLASH_SMEM 54784
__global__ __launch_bounds__(128) void flash_attn(
    const __half* __restrict__ q, const __half* __restrict__ k,
    const float* __restrict__ v, const __half* __restrict__ pkn_l,
    const int* __restrict__ masks, __half* __restrict__ o)
{
    extern __shared__ char sbuf[];
    unsigned* Vs = (unsigned*)sbuf;
    unsigned* Kh = (unsigned*)(sbuf + 18944);
    unsigned* Ph = (unsigned*)(sbuf + 28160);
    float*    Rs = (float*)(sbuf + 18944);
    unsigned* Ru = (unsigned*)(sbuf + 18944);
    int*      msk = (int*)(sbuf + 52736);

    int tid = threadIdx.x;
    int lane = tid & 31, warp = tid >> 5;
    int g = lane >> 2, tg = lane & 3;
    int rl0 = warp * 16 + g, rl1 = rl0 + 8;

    int cBr = lane & 7;
    int cBs = ((lane >> 4) & 1);
    int kBw = ((lane >> 3) & 1) * 4;

    int t0 = blockIdx.x * 64, bh = blockIdx.y;
    int b = bh >> 2, h = bh & 3;
    const __half* qb  = q + ((size_t)(b * T_ + t0)) * D_ + h * DK;
    const __half* kb0 = k + ((size_t)(b * T_)) * D_ + h * DK;
    const float*  vb0 = v + ((size_t)(b * T_)) * D_ + h * DK;

    #pragma unroll
    for (int i = 0; i < 4; i++) msk[tid + i * 128] = masks[b * T_ + tid + i * 128];
    #pragma unroll
    for (int i = 0; i < 4; i++) {
        int idx = tid + i * 128, r = idx >> 3, c8 = idx & 7;
        uint4 w = *(const uint4*)&qb[(size_t)r * D_ + c8 * 8];
        *(uint4*)&Kh[r * KSTRH + c8 * 4] = w;
    }
    __syncthreads();
    unsigned qa[4][4];
    #pragma unroll
    for (int ks = 0; ks < 4; ks++) {
        qa[ks][0] = Kh[rl0 * KSTRH + ks * 8 + tg];
        qa[ks][1] = Kh[rl1 * KSTRH + ks * 8 + tg];
        qa[ks][2] = Kh[rl0 * KSTRH + ks * 8 + tg + 4];
        qa[ks][3] = Kh[rl1 * KSTRH + ks * 8 + tg + 4];
    }
    __syncthreads();

    float accO[8][4];
    #pragma unroll
    for (int nt = 0; nt < 8; nt++)
        #pragma unroll
        for (int e = 0; e < 4; e++) accO[nt][e] = 0.0f;
    float m0 = -FLT_MAX, m1 = -FLT_MAX, l0 = 0.0f, l1 = 0.0f;

    const float scale = 0.125f;

    for (int sc = 0; sc < 8; sc++) {
        int s0 = sc * 64;
        #pragma unroll
        for (int i = 0; i < 4; i++) {
            int idx = tid + i * 128, r = idx >> 3, c8 = idx & 7;
            uint4 w = *(const uint4*)&kb0[(size_t)(s0 + r) * D_ + c8 * 8];
            *(uint4*)&Kh[r * KSTRH + c8 * 4] = w;
        }
        #pragma unroll
        for (int i = 0; i < 8; i++) {
            int idx = tid + i * 128, r = idx >> 4, c4 = idx & 15;
            int half = r >> 5, rsl = r & 31;
            unsigned* vp = &Vs[half * VPANE];
            float4 vv = *(const float4*)&vb0[(size_t)(s0 + r) * D_ + c4 * 4];
            vp[(c4 * 4 + 0) * VSTR + rsl] = f2tf(vv.x);
            vp[(c4 * 4 + 1) * VSTR + rsl] = f2tf(vv.y);
            vp[(c4 * 4 + 2) * VSTR + rsl] = f2tf(vv.z);
            vp[(c4 * 4 + 3) * VSTR + rsl] = f2tf(vv.w);
        }
        const __half* pb = pkn_l + (size_t)(t0 - s0 + 448) * DK;
        #pragma unroll
        for (int i = 0; i < 8; i++) {
            int idx = tid + i * 128, r = idx >> 3, c8 = idx & 7;
            uint4 w;
            if (r < 127) w = *(const uint4*)&pb[(size_t)r * DK + c8 * 8];
            else { w.x = 0u; w.y = 0u; w.z = 0u; w.w = 0u; }
            *(uint4*)&Ph[r * KSTRH + c8 * 4] = w;
        }
        __syncthreads();

        float accS[8][4], accR[16][4];
        #pragma unroll
        for (int nt = 0; nt < 8; nt++)
            #pragma unroll
            for (int e = 0; e < 4; e++) accS[nt][e] = 0.0f;
        #pragma unroll
        for (int nt = 0; nt < 16; nt++)
            #pragma unroll
            for (int e = 0; e < 4; e++) accR[nt][e] = 0.0f;

        #pragma unroll
        for (int ks = 0; ks < 4; ks++) {
            int ko = ks * 8;
            #pragma unroll
            for (int np = 0; np < 4; np++) {
                int col = (np * 2 + cBs) * 8 + cBr;
                unsigned q0, q1, q2, q3;
                ldsm4(q0, q1, q2, q3, sptr(&Kh[col * KSTRH + ko + kBw]));
                mma_f16(accS[np * 2],     qa[ks][0], qa[ks][1], qa[ks][2], qa[ks][3], q0, q1);
                mma_f16(accS[np * 2 + 1], qa[ks][0], qa[ks][1], qa[ks][2], qa[ks][3], q2, q3);
            }
            #pragma unroll
            for (int np = 0; np < 8; np++) {
                int col = (np * 2 + cBs) * 8 + cBr;
                unsigned q0, q1, q2, q3;
                ldsm4(q0, q1, q2, q3, sptr(&Ph[col * KSTRH + ko + kBw]));
                mma_f16(accR[np * 2],     qa[ks][0], qa[ks][1], qa[ks][2], qa[ks][3], q0, q1);
                mma_f16(accR[np * 2 + 1], qa[ks][0], qa[ks][1], qa[ks][2], qa[ks][3], q2, q3);
            }
        }
        __syncthreads();   // Kh/Ph reads complete before Rs overwrite

        #pragma unroll
        for (int nt = 0; nt < 16; nt++) {
            int col = nt * 8 + 2 * tg;
            Rs[rl0 * 132 + col]     = accR[nt][0];
            Rs[rl0 * 132 + col + 1] = accR[nt][1];
            Rs[rl1 * 132 + col]     = accR[nt][2];
            Rs[rl1 * 132 + col + 1] = accR[nt][3];
        }
        __syncwarp();

        #pragma unroll
        for (int nt = 0; nt < 8; nt++) {
            #pragma unroll
            for (int e = 0; e < 2; e++) {
                int c = nt * 8 + 2 * tg + e;
                float r0 = Rs[rl0 * 132 + (rl0 - c + 63)];
                float r1 = Rs[rl1 * 132 + (rl1 - c + 63)];
                float x0 = (accS[nt][e] + r0) * scale;
                float x1 = (accS[nt][2 + e] + r1) * scale;
                if (msk[s0 + c] == 0) { x0 = -FLT_MAX; x1 = -FLT_MAX; }
                accS[nt][e] = x0;
                accS[nt][2 + e] = x1;
            }
        }
        __syncwarp();

        float cm0 = -FLT_MAX, cm1 = -FLT_MAX;
        #pragma unroll
        for (int nt = 0; nt < 8; nt++) {
            cm0 = fmaxf(cm0, fmaxf(accS[nt][0], accS[nt][1]));
            cm1 = fmaxf(cm1, fmaxf(accS[nt][2], accS[nt][3]));
        }
        cm0 = fmaxf(cm0, __shfl_xor_sync(0xffffffffu, cm0, 1));
        cm0 = fmaxf(cm0, __shfl_xor_sync(0xffffffffu, cm0, 2));
        cm1 = fmaxf(cm1, __shfl_xor_sync(0xffffffffu, cm1, 1));
        cm1 = fmaxf(cm1, __shfl_xor_sync(0xffffffffu, cm1, 2));

        float nm0 = fmaxf(m0, cm0), nm1 = fmaxf(m1, cm1);
        float al0 = __expf(m0 - nm0), al1 = __expf(m1 - nm1);
        float cs0 = 0.0f, cs1 = 0.0f;
        #pragma unroll
        for (int nt = 0; nt < 8; nt++) {
            accS[nt][0] = __expf(accS[nt][0] - nm0);
            accS[nt][1] = __expf(accS[nt][1] - nm0);
            accS[nt][2] = __expf(accS[nt][2] - nm1);
            accS[nt][3] = __expf(accS[nt][3] - nm1);
            cs0 += accS[nt][0] + accS[nt][1];
            cs1 += accS[nt][2] + accS[nt][3];
        }
        cs0 += __shfl_xor_sync(0xffffffffu, cs0, 1);
        cs0 += __shfl_xor_sync(0xffffffffu, cs0, 2);
        cs1 += __shfl_xor_sync(0xffffffffu, cs1, 1);
        cs1 += __shfl_xor_sync(0xffffffffu, cs1, 2);
        l0 = l0 * al0 + cs0;
        l1 = l1 * al1 + cs1;
        m0 = nm0; m1 = nm1;

        #pragma unroll
        for (int nt = 0; nt < 8; nt++) {
            accO[nt][0] *= al0; accO[nt][1] *= al0;
            accO[nt][2] *= al1; accO[nt][3] *= al1;
        }

        #pragma unroll
        for (int nt = 0; nt < 8; nt++) {
            int col = nt * 8 + 2 * tg;
            Ru[rl0 * 132 + col]     = f2tf(accS[nt][0]);
            Ru[rl0 * 132 + col + 1] = f2tf(accS[nt][1]);
            Ru[rl1 * 132 + col]     = f2tf(accS[nt][2]);
            Ru[rl1 * 132 + col + 1] = f2tf(accS[nt][3]);
        }
        __syncwarp();

        #pragma unroll
        for (int kc = 0; kc < 8; kc++) {
            int ko = kc * 8;
            const unsigned* vp = &Vs[(kc >> 2) * VPANE];
            int so = ko & 31;
            unsigned a0 = Ru[rl0 * 132 + ko + tg];
            unsigned a1 = Ru[rl1 * 132 + ko + tg];
            unsigned a2 = Ru[rl0 * 132 + ko + tg + 4];
            unsigned a3 = Ru[rl1 * 132 + ko + tg + 4];
            #pragma unroll
            for (int nt = 0; nt < 8; nt++) {
                int col = nt * 8 + g;
                unsigned b0 = vp[col * VSTR + so + tg];
                unsigned b1 = vp[col * VSTR + so + tg + 4];
                mma_tf32(accO[nt], a0, a1, a2, a3, b0, b1);
            }
        }
        __syncthreads();
    }

    float inv0 = 1.0f / l0, inv1 = 1.0f / l1;
    #pragma unroll
    for (int nt = 0; nt < 8; nt++) {
        int col = nt * 8 + 2 * tg;
        *(unsigned*)&o[((size_t)(b * T_ + t0 + rl0)) * D_ + h * DK + col] =
            pack_h2(accO[nt][0] * inv0, accO[nt][1] * inv0);
        *(unsigned*)&o[((size_t)(b * T_ + t0 + rl1)) * D_ + h * DK + col] =
            pack_h2(accO[nt][2] * inv1, accO[nt][3] * inv1);
    }
}

// ------------------------- host orchestration -------------------------
extern "C" void kernel_launch(void* const* d_in, const int* in_sizes, int n_in,
                              void* d_out, int out_size) {
    const float* xs      = (const float*)d_in[0];
    const int*   masks   = (const int*)  d_in[1];
    const float* emb_w   = (const float*)d_in[2];
    const float* emb_b   = (const float*)d_in[3];
    const float* emb_g   = (const float*)d_in[4];
    const float* emb_bt  = (const float*)d_in[5];
    const float* pe_k    = (const float*)d_in[6];
    const float* Wq      = (const float*)d_in[7];
    const float* bq      = (const float*)d_in[8];
    const float* Wk      = (const float*)d_in[9];
    const float* bk      = (const float*)d_in[10];
    const float* Wv      = (const float*)d_in[11];
    const float* bv      = (const float*)d_in[12];
    const float* Wo      = (const float*)d_in[13];
    const float* bo      = (const float*)d_in[14];
    const float* ln1_g   = (const float*)d_in[15];
    const float* ln1_b   = (const float*)d_in[16];
    const float* ln2_g   = (const float*)d_in[17];
    const float* ln2_b   = (const float*)d_in[18];
    const float* lnk_g   = (const float*)d_in[19];
    const float* lnk_b   = (const float*)d_in[20];
    const float* W1      = (const float*)d_in[21];
    const float* b1      = (const float*)d_in[22];
    const float* W2      = (const float*)d_in[23];
    const float* b2      = (const float*)d_in[24];
    const float* after_g = (const float*)d_in[25];
    const float* after_b = (const float*)d_in[26];
    float* out = (float*)d_out;

    float *x, *y, *v, *mu, *rs;
    __half *oh, *qh, *kh, *ffh, *pkn, *hemb, *hq, *hk, *hv, *ho, *h1, *h2;
    cudaGetSymbolAddress((void**)&x,    g_x);
    cudaGetSymbolAddress((void**)&y,    g_y);
    cudaGetSymbolAddress((void**)&v,    g_v);
    cudaGetSymbolAddress((void**)&mu,   g_mu);
    cudaGetSymbolAddress((void**)&rs,   g_rs);
    cudaGetSymbolAddress((void**)&oh,   g_oh);
    cudaGetSymbolAddress((void**)&qh,   g_qh);
    cudaGetSymbolAddress((void**)&kh,   g_kh);
    cudaGetSymbolAddress((void**)&ffh,  g_ffh);
    cudaGetSymbolAddress((void**)&pkn,  g_pkn);
    cudaGetSymbolAddress((void**)&hemb, g_hemb);
    cudaGetSymbolAddress((void**)&hq,   g_hq);
    cudaGetSymbolAddress((void**)&hk,   g_hk);
    cudaGetSymbolAddress((void**)&hv,   g_hv);
    cudaGetSymbolAddress((void**)&ho,   g_ho);
    cudaGetSymbolAddress((void**)&h1,   g_h1);
    cudaGetSymbolAddress((void**)&h2,   g_h2);

    cudaFuncSetAttribute(flash_attn, cudaFuncAttributeMaxDynamicSharedMemorySize, FLASH_SMEM);

    auto conv = [](const float* src, __half* dst, size_t n) {
        int n4 = (int)(n / 4);
        f2h<<<(n4 + 255) / 256, 256>>>(src, dst, n4);
    };
    conv(emb_w, hemb, (size_t)D_ * IDIM);
    conv(Wq, hq, (size_t)L_ * D_ * D_);
    conv(Wk, hk, (size_t)L_ * D_ * D_);
    conv(Wv, hv, (size_t)L_ * D_ * D_);
    conv(Wo, ho, (size_t)L_ * D_ * D_);
    conv(W1, h1, (size_t)L_ * FF_ * D_);
    conv(W2, h2, (size_t)L_ * D_ * FF_);

    dim3 gProj(D_ / 64, BT / 128);       // (4, 32)
    dim3 gQKV(D_ / 64, BT / 128, 3);     // (4, 32, 3)
    dim3 gFF1(FF_ / 128, BT / 128);      // (16, 32)

    tgemm128_f<<<gProj, 256>>>(xs, hemb, emb_b, nullptr, y, D_, IDIM, 0);
    ln_pkn_all<<<dim3(NPK, L_), 64>>>(pe_k, pkn, lnk_g, lnk_b);
    ln_warp<<<BT / 8, 256>>>(y, x, emb_g, emb_bt, 1);

    for (int l = 0; l < L_; l++) {
        ln_stats<<<BT / 8, 256>>>(x, mu, rs);
        tgemm128_qkv<<<gQKV, 256>>>(x,
            hq + (size_t)l * D_ * D_, hk + (size_t)l * D_ * D_, hv + (size_t)l * D_ * D_,
            bq + l * D_, bk + l * D_, bv + l * D_, qh, kh, v,
            mu, rs, ln1_g + l * D_, ln1_b + l * D_);

        flash_attn<<<dim3(8, BH), 128, FLASH_SMEM>>>(qh, kh, v,
            pkn + (size_t)l * NPK * DK, masks, oh);

        tgemm128_h<<<gProj, 256>>>(oh, ho + (size_t)l * D_ * D_, bo + l * D_, x, x, D_, D_, 2);

        ln_stats<<<BT / 8, 256>>>(x, mu, rs);
        tgemm256<<<gFF1, 256>>>(x, h1 + (size_t)l * FF_ * D_, b1 + l * FF_, ffh,
                                FF_, D_, 1, mu, rs, ln2_g + l * D_, ln2_b + l * D_);
        tgemm128_h<<<gProj, 256>>>(ffh, h2 + (size_t)l * D_ * FF_, b2 + l * D_, x, x, D_, FF_, 2);
    }

    ln_warp<<<BT / 8, 256>>>(x, out, after_g, after_b, 0);
}

// round 16
// speedup vs baseline: 1.0286x; 1.0286x over previous
#include <cuda_runtime.h>
#include <cuda_fp16.h>
#include <math.h>
#include <float.h>

// Problem constants
#define B_    8
#define T_    512
#define IDIM  1799
#define D_    256
#define H_    4
#define FF_   2048
#define L_    16
#define DK    64
#define BT    (B_*T_)    // 4096
#define BH    (B_*H_)    // 32
#define NPK   1023       // distinct rel-pos rows: t-s+511 in [0,1022]

// ------------------------- scratch (device globals) -------------------------
__device__ float g_x[BT*D_];
__device__ float g_y[BT*D_];
__device__ float g_v[BT*D_];
__device__ float2 g_pstat[8*BT];       // 8 partial (sum, sumsq) slots per row
__device__ __half g_oh[BT*D_];
__device__ __half g_qh[BT*D_];
__device__ __half g_kh[BT*D_];
__device__ __half g_ffh[(size_t)BT*FF_];
__device__ __half g_pkn[(size_t)L_*NPK*DK];
// fp16 weights
__device__ __half g_hemb[D_*IDIM];
__device__ __half g_hq[(size_t)L_*D_*D_];
__device__ __half g_hk[(size_t)L_*D_*D_];
__device__ __half g_hv[(size_t)L_*D_*D_];
__device__ __half g_ho[(size_t)L_*D_*D_];
__device__ __half g_h1[(size_t)L_*FF_*D_];
__device__ __half g_h2[(size_t)L_*D_*FF_];

// ------------------------- helpers -------------------------
__device__ __forceinline__ unsigned f2tf(float f) {
    unsigned r;
    asm("cvt.rna.tf32.f32 %0, %1;" : "=r"(r) : "f"(f));
    return r;
}
__device__ __forceinline__ unsigned pack_h2(float lo, float hi) {
    unsigned u;
    asm("cvt.rn.f16x2.f32 %0, %1, %2;" : "=r"(u) : "f"(hi), "f"(lo));
    return u;
}
__device__ __forceinline__ void mma_tf32(float c[4],
                                         unsigned a0, unsigned a1, unsigned a2, unsigned a3,
                                         unsigned b0, unsigned b1) {
    asm volatile(
        "mma.sync.aligned.m16n8k8.row.col.f32.tf32.tf32.f32 "
        "{%0,%1,%2,%3}, {%4,%5,%6,%7}, {%8,%9}, {%0,%1,%2,%3};"
        : "+f"(c[0]), "+f"(c[1]), "+f"(c[2]), "+f"(c[3])
        : "r"(a0), "r"(a1), "r"(a2), "r"(a3), "r"(b0), "r"(b1));
}
__device__ __forceinline__ void mma_f16(float c[4],
                                        unsigned a0, unsigned a1, unsigned a2, unsigned a3,
                                        unsigned b0, unsigned b1) {
    asm volatile(
        "mma.sync.aligned.m16n8k16.row.col.f32.f16.f16.f32 "
        "{%0,%1,%2,%3}, {%4,%5,%6,%7}, {%8,%9}, {%0,%1,%2,%3};"
        : "+f"(c[0]), "+f"(c[1]), "+f"(c[2]), "+f"(c[3])
        : "r"(a0), "r"(a1), "r"(a2), "r"(a3), "r"(b0), "r"(b1));
}

// combine 8 partial stats -> (mean, rstd)
__device__ __forceinline__ void combine_stats(const float2* __restrict__ ps, int row,
                                              float& mean, float& rstd) {
    float s = 0.0f, q = 0.0f;
    #pragma unroll
    for (int j = 0; j < 8; j++) {
        float2 p = ps[(size_t)j * BT + row];
        s += p.x; q += p.y;
    }
    mean = s * (1.0f / 256.0f);
    float var = q * (1.0f / 256.0f) - mean * mean;
    rstd = rsqrtf(var + 1e-12f);
}

// ------------------------- fp32 -> fp16 bulk convert -------------------------
__global__ __launch_bounds__(256) void f2h(const float* __restrict__ in,
                                           __half* __restrict__ out, int n4) {
    int i = blockIdx.x * 256 + threadIdx.x;
    if (i < n4) {
        float4 v = *(const float4*)&in[i * 4];
        uint2 o;
        o.x = pack_h2(v.x, v.y);
        o.y = pack_h2(v.z, v.w);
        *(uint2*)&out[i * 4] = o;
    }
}

// ------------------------- block reduction (for pkn LN only) -------------------------
__device__ __forceinline__ float block_sum64(float v) {
    __shared__ float sh[3];
    #pragma unroll
    for (int o = 16; o > 0; o >>= 1) v += __shfl_xor_sync(0xffffffffu, v, o);
    int lane = threadIdx.x & 31, w = threadIdx.x >> 5;
    if (lane == 0) sh[w] = v;
    __syncthreads();
    float out = sh[0] + sh[1];
    __syncthreads();
    return out;
}

// all-layers pkn LN -> fp16: grid (NPK, L), block 64
__global__ void ln_pkn_all(const float* __restrict__ pe_k, __half* __restrict__ pkn,
                           const float* __restrict__ lnk_g, const float* __restrict__ lnk_b) {
    int row = blockIdx.x, l = blockIdx.y;
    float x = pe_k[(size_t)(489 + row) * DK + threadIdx.x];
    float mean = block_sum64(x) / (float)DK;
    float d = x - mean;
    float var = block_sum64(d * d) / (float)DK;
    float y = d * rsqrtf(var + 1e-12f) * lnk_g[l * DK + threadIdx.x] + lnk_b[l * DK + threadIdx.x];
    pkn[((size_t)l * NPK + row) * DK + threadIdx.x] = __float2half_rn(y);
}

// ------------------------- warp-per-row LayerNorm, width 256 -------------------------
// If pstat != nullptr, also emit (sum,sumsq) of the OUTPUT into slot 0, zero slots 1..7.
__global__ __launch_bounds__(256) void ln_warp(const float* __restrict__ in,
                                               float* __restrict__ out,
                                               const float* __restrict__ g,
                                               const float* __restrict__ bb,
                                               int relu, float2* __restrict__ pstat) {
    int warp = threadIdx.x >> 5, lane = threadIdx.x & 31;
    size_t row = (size_t)blockIdx.x * 8 + warp;
    const float* ip = in + row * D_;
    float4 v0 = *(const float4*)&ip[lane * 4];
    float4 v1 = *(const float4*)&ip[128 + lane * 4];
    float s = v0.x + v0.y + v0.z + v0.w + v1.x + v1.y + v1.z + v1.w;
    #pragma unroll
    for (int o = 16; o > 0; o >>= 1) s += __shfl_xor_sync(0xffffffffu, s, o);
    float mean = s * (1.0f / 256.0f);
    float d0x = v0.x - mean, d0y = v0.y - mean, d0z = v0.z - mean, d0w = v0.w - mean;
    float d1x = v1.x - mean, d1y = v1.y - mean, d1z = v1.z - mean, d1w = v1.w - mean;
    float vs = d0x*d0x + d0y*d0y + d0z*d0z + d0w*d0w + d1x*d1x + d1y*d1y + d1z*d1z + d1w*d1w;
    #pragma unroll
    for (int o = 16; o > 0; o >>= 1) vs += __shfl_xor_sync(0xffffffffu, vs, o);
    float rstd = rsqrtf(vs * (1.0f / 256.0f) + 1e-12f);
    float4 g0 = *(const float4*)&g[lane * 4];
    float4 g1 = *(const float4*)&g[128 + lane * 4];
    float4 b0 = *(const float4*)&bb[lane * 4];
    float4 b1 = *(const float4*)&bb[128 + lane * 4];
    float4 o0, o1;
    o0.x = d0x * rstd * g0.x + b0.x;  o0.y = d0y * rstd * g0.y + b0.y;
    o0.z = d0z * rstd * g0.z + b0.z;  o0.w = d0w * rstd * g0.w + b0.w;
    o1.x = d1x * rstd * g1.x + b1.x;  o1.y = d1y * rstd * g1.y + b1.y;
    o1.z = d1z * rstd * g1.z + b1.z;  o1.w = d1w * rstd * g1.w + b1.w;
    if (relu) {
        o0.x = fmaxf(o0.x, 0.f); o0.y = fmaxf(o0.y, 0.f); o0.z = fmaxf(o0.z, 0.f); o0.w = fmaxf(o0.w, 0.f);
        o1.x = fmaxf(o1.x, 0.f); o1.y = fmaxf(o1.y, 0.f); o1.z = fmaxf(o1.z, 0.f); o1.w = fmaxf(o1.w, 0.f);
    }
    float* op = out + row * D_;
    *(float4*)&op[lane * 4] = o0;
    *(float4*)&op[128 + lane * 4] = o1;

    if (pstat) {
        float ss = o0.x + o0.y + o0.z + o0.w + o1.x + o1.y + o1.z + o1.w;
        float qq = o0.x*o0.x + o0.y*o0.y + o0.z*o0.z + o0.w*o0.w
                 + o1.x*o1.x + o1.y*o1.y + o1.z*o1.z + o1.w*o1.w;
        #pragma unroll
        for (int o = 16; o > 0; o >>= 1) {
            ss += __shfl_xor_sync(0xffffffffu, ss, o);
            qq += __shfl_xor_sync(0xffffffffu, qq, o);
        }
        if (lane == 0) {
            pstat[row] = make_float2(ss, qq);
            #pragma unroll
            for (int j = 1; j < 8; j++)
                pstat[(size_t)j * BT + row] = make_float2(0.0f, 0.0f);
        }
    }
}

// ------------------------- FP16 GEMM body, BM=128 BN=64 BK=32 -------------------------
// B always fp16. A fp32 (+opt fused LN via partial stats) or fp16 (template AH).
// C fp32 (+opt residual) or fp16. Optionally emits partial row stats of C (psout).
#define STRH 20
template<bool AH>
__device__ __forceinline__ void tg128_body(
    const void* __restrict__ Ap, const __half* __restrict__ Bm,
    const float* __restrict__ bias, const float* __restrict__ R,
    void* __restrict__ Cp, int N, int K, int mode, int c_half, int r0, int c0,
    const float2* __restrict__ psin,
    const float* __restrict__ lg, const float* __restrict__ lb,
    float2* __restrict__ psout, int pslot)
{
    __shared__ unsigned As[128 * STRH];
    __shared__ unsigned Bs[64 * STRH];

    int tid = threadIdx.x;
    int lane = tid & 31, warp = tid >> 5;
    int wm = warp >> 1, wn = warp & 1;
    int g = lane >> 2, tg = lane & 3;

    const float*  Af = AH ? nullptr : (const float*)Ap + (size_t)r0 * K;
    const __half* Ah = AH ? (const __half*)Ap + (size_t)r0 * K : nullptr;
    const __half* Bb = Bm + (size_t)c0 * K;

    float acc[2][4][4];
    #pragma unroll
    for (int mt = 0; mt < 2; mt++)
        #pragma unroll
        for (int nt = 0; nt < 4; nt++)
            #pragma unroll
            for (int e = 0; e < 4; e++) acc[mt][nt][e] = 0.0f;

    float muv[4], rsv[4];
    if (!AH && lg) {
        #pragma unroll
        for (int i = 0; i < 4; i++) {
            int r = (tid + i * 256) >> 3;
            combine_stats(psin, r0 + r, muv[i], rsv[i]);
        }
    }

    auto do_mma = [&]() {
        #pragma unroll
        for (int kc = 0; kc < 2; kc++) {
            int ko = kc * 8;
            unsigned a[2][4], b[4][2];
            #pragma unroll
            for (int mt = 0; mt < 2; mt++) {
                int row = wm * 32 + mt * 16 + g;
                a[mt][0] = As[row * STRH + ko + tg];
                a[mt][1] = As[(row + 8) * STRH + ko + tg];
                a[mt][2] = As[row * STRH + ko + tg + 4];
                a[mt][3] = As[(row + 8) * STRH + ko + tg + 4];
            }
            #pragma unroll
            for (int nt = 0; nt < 4; nt++) {
                int col = wn * 32 + nt * 8 + g;
                b[nt][0] = Bs[col * STRH + ko + tg];
                b[nt][1] = Bs[col * STRH + ko + tg + 4];
            }
            #pragma unroll
            for (int mt = 0; mt < 2; mt++)
                #pragma unroll
                for (int nt = 0; nt < 4; nt++)
                    mma_f16(acc[mt][nt], a[mt][0], a[mt][1], a[mt][2], a[mt][3],
                            b[nt][0], b[nt][1]);
        }
    };

    if ((K & 31) == 0) {
        int nch = K >> 5;
        int br = tid >> 2, bc8 = tid & 3;
        uint4 pbh = *(const uint4*)&Bb[(size_t)br * K + bc8 * 8];

        if (AH) {
            uint4 pah[2];
            #pragma unroll
            for (int i = 0; i < 2; i++) {
                int idx = tid + i * 256, r = idx >> 2, c8 = idx & 3;
                pah[i] = *(const uint4*)&Ah[(size_t)r * K + c8 * 8];
            }
            #pragma unroll
            for (int i = 0; i < 2; i++) {
                int idx = tid + i * 256, r = idx >> 2, c8 = idx & 3;
                *(uint4*)&As[r * STRH + c8 * 4] = pah[i];
            }
            *(uint4*)&Bs[br * STRH + bc8 * 4] = pbh;
            __syncthreads();
            for (int ch = 0; ch < nch; ch++) {
                bool more = (ch + 1 < nch);
                int k1 = (ch + 1) << 5;
                if (more) {
                    #pragma unroll
                    for (int i = 0; i < 2; i++) {
                        int idx = tid + i * 256, r = idx >> 2, c8 = idx & 3;
                        pah[i] = *(const uint4*)&Ah[(size_t)r * K + k1 + c8 * 8];
                    }
                    pbh = *(const uint4*)&Bb[(size_t)br * K + k1 + bc8 * 8];
                }
                do_mma();
                if (more) {
                    __syncthreads();
                    #pragma unroll
                    for (int i = 0; i < 2; i++) {
                        int idx = tid + i * 256, r = idx >> 2, c8 = idx & 3;
                        *(uint4*)&As[r * STRH + c8 * 4] = pah[i];
                    }
                    *(uint4*)&Bs[br * STRH + bc8 * 4] = pbh;
                    __syncthreads();
                }
            }
        } else {
            float4 pa[4];
            #pragma unroll
            for (int i = 0; i < 4; i++) {
                int idx = tid + i * 256, r = idx >> 3, c4 = idx & 7;
                pa[i] = *(const float4*)&Af[(size_t)r * K + c4 * 4];
            }
            auto store_a = [&](float4 av, int i, int kbase) {
                int idx = tid + i * 256, r = idx >> 3, c4 = idx & 7;
                if (lg) {
                    float4 ga = *(const float4*)&lg[kbase + c4 * 4];
                    float4 be = *(const float4*)&lb[kbase + c4 * 4];
                    float m = muv[i], rr = rsv[i];
                    av.x = (av.x - m) * rr * ga.x + be.x;
                    av.y = (av.y - m) * rr * ga.y + be.y;
                    av.z = (av.z - m) * rr * ga.z + be.z;
                    av.w = (av.w - m) * rr * ga.w + be.w;
                }
                unsigned* ap = &As[r * STRH + c4 * 2];
                ap[0] = pack_h2(av.x, av.y);
                ap[1] = pack_h2(av.z, av.w);
            };
            #pragma unroll
            for (int i = 0; i < 4; i++) store_a(pa[i], i, 0);
            *(uint4*)&Bs[br * STRH + bc8 * 4] = pbh;
            __syncthreads();
            for (int ch = 0; ch < nch; ch++) {
                bool more = (ch + 1 < nch);
                int k1 = (ch + 1) << 5;
                if (more) {
                    #pragma unroll
                    for (int i = 0; i < 4; i++) {
                        int idx = tid + i * 256, r = idx >> 3, c4 = idx & 7;
                        pa[i] = *(const float4*)&Af[(size_t)r * K + k1 + c4 * 4];
                    }
                    pbh = *(const uint4*)&Bb[(size_t)br * K + k1 + bc8 * 8];
                }
                do_mma();
                if (more) {
                    __syncthreads();
                    #pragma unroll
                    for (int i = 0; i < 4; i++) store_a(pa[i], i, k1);
                    *(uint4*)&Bs[br * STRH + bc8 * 4] = pbh;
                    __syncthreads();
                }
            }
        }
    } else {
        // guarded scalar path (embed GEMM, K=1799): A fp32, B fp16
        for (int k0 = 0; k0 < K; k0 += 32) {
            #pragma unroll
            for (int i = 0; i < 8; i++) {
                int idx = tid + i * 256, r = idx >> 4, c2 = idx & 15;
                int kk = k0 + c2 * 2;
                float f0 = (kk < K)     ? Af[(size_t)r * K + kk]     : 0.0f;
                float f1 = (kk + 1 < K) ? Af[(size_t)r * K + kk + 1] : 0.0f;
                As[r * STRH + c2] = pack_h2(f0, f1);
            }
            #pragma unroll
            for (int i = 0; i < 4; i++) {
                int idx = tid + i * 256, r = idx >> 4, c2 = idx & 15;
                int kk = k0 + c2 * 2;
                float f0 = (kk < K)     ? __half2float(Bb[(size_t)r * K + kk])     : 0.0f;
                float f1 = (kk + 1 < K) ? __half2float(Bb[(size_t)r * K + kk + 1]) : 0.0f;
                Bs[r * STRH + c2] = pack_h2(f0, f1);
            }
            __syncthreads();
            do_mma();
            __syncthreads();
        }
    }

    float ps_[2][2], pq_[2][2];
    #pragma unroll
    for (int mt = 0; mt < 2; mt++)
        #pragma unroll
        for (int hf = 0; hf < 2; hf++) { ps_[mt][hf] = 0.0f; pq_[mt][hf] = 0.0f; }

    #pragma unroll
    for (int mt = 0; mt < 2; mt++) {
        int row = r0 + wm * 32 + mt * 16 + g;
        #pragma unroll
        for (int nt = 0; nt < 4; nt++) {
            int col = c0 + wn * 32 + nt * 8 + 2 * tg;
            float2 bi = *(const float2*)&bias[col];
            #pragma unroll
            for (int half = 0; half < 2; half++) {
                int rr = row + half * 8;
                float x0 = acc[mt][nt][half * 2 + 0] + bi.x;
                float x1 = acc[mt][nt][half * 2 + 1] + bi.y;
                if (mode & 2) {
                    float2 rv = *(const float2*)&R[(size_t)rr * N + col];
                    x0 += rv.x; x1 += rv.y;
                }
                if (mode & 1) { x0 = fmaxf(x0, 0.0f); x1 = fmaxf(x1, 0.0f); }
                if (psout) {
                    ps_[mt][half] += x0 + x1;
                    pq_[mt][half] += x0 * x0 + x1 * x1;
                }
                if (c_half) {
                    *(unsigned*)&((__half*)Cp)[(size_t)rr * N + col] = pack_h2(x0, x1);
                } else {
                    float2 o2 = {x0, x1};
                    *(float2*)&((float*)Cp)[(size_t)rr * N + col] = o2;
                }
            }
        }
    }

    if (psout) {
        #pragma unroll
        for (int mt = 0; mt < 2; mt++)
            #pragma unroll
            for (int hf = 0; hf < 2; hf++) {
                float s = ps_[mt][hf], q = pq_[mt][hf];
                s += __shfl_xor_sync(0xffffffffu, s, 1);
                s += __shfl_xor_sync(0xffffffffu, s, 2);
                q += __shfl_xor_sync(0xffffffffu, q, 1);
                q += __shfl_xor_sync(0xffffffffu, q, 2);
                if (tg == 0) {
                    int row = r0 + wm * 32 + mt * 16 + g + hf * 8;
                    psout[(size_t)(pslot + wn) * BT + row] = make_float2(s, q);
                }
            }
    }
}

__global__ __launch_bounds__(256) void tgemm128_f(
    const float* __restrict__ A, const __half* __restrict__ Bm,
    const float* __restrict__ bias, const float* __restrict__ R,
    float* __restrict__ C, int N, int K, int mode)
{
    tg128_body<false>(A, Bm, bias, R, C, N, K, mode, 0,
                      blockIdx.y * 128, blockIdx.x * 64,
                      nullptr, nullptr, nullptr, nullptr, 0);
}

// fp16-A GEMM; optionally emits partial row stats of C
__global__ __launch_bounds__(256) void tgemm128_h(
    const __half* __restrict__ A, const __half* __restrict__ Bm,
    const float* __restrict__ bias, const float* __restrict__ R,
    float* __restrict__ C, int N, int K, int mode, float2* __restrict__ psout)
{
    tg128_body<true>(A, Bm, bias, R, C, N, K, mode, 0,
                     blockIdx.y * 128, blockIdx.x * 64,
                     nullptr, nullptr, nullptr, psout, blockIdx.x * 2);
}

// batched Q/K/V with LN-from-partial-stats: z=0 -> q fp16, z=1 -> k fp16, z=2 -> v fp32
__global__ __launch_bounds__(256) void tgemm128_qkv(
    const float* __restrict__ A,
    const __half* __restrict__ Wq, const __half* __restrict__ Wk, const __half* __restrict__ Wv,
    const float* __restrict__ bq, const float* __restrict__ bk, const float* __restrict__ bv,
    __half* __restrict__ qh, __half* __restrict__ kh, float* __restrict__ v,
    const float2* __restrict__ psin,
    const float* __restrict__ lg, const float* __restrict__ lb)
{
    const __half* W; const float* bi; void* C; int ch;
    if (blockIdx.z == 0)      { W = Wq; bi = bq; C = qh; ch = 1; }
    else if (blockIdx.z == 1) { W = Wk; bi = bk; C = kh; ch = 1; }
    else                      { W = Wv; bi = bv; C = v;  ch = 0; }
    tg128_body<false>(A, W, bi, nullptr, C, D_, D_, 0, ch,
                      blockIdx.y * 128, blockIdx.x * 64, psin, lg, lb, nullptr, 0);
}

// ------------------------- FP16 GEMM, BM=128 BN=128 BK=32 (FF1, fp16 out) -----------------
__global__ __launch_bounds__(256) void tgemm256(
    const float* __restrict__ A, const __half* __restrict__ Bm,
    const float* __restrict__ bias, __half* __restrict__ C,
    int N, int K, int mode,
    const float2* __restrict__ psin,
    const float* __restrict__ lg, const float* __restrict__ lb)
{
    __shared__ unsigned As[128 * STRH];
    __shared__ unsigned Bs[128 * STRH];

    int tid = threadIdx.x;
    int lane = tid & 31, warp = tid >> 5;
    int wm = warp >> 2, wn = warp & 3;
    int g = lane >> 2, tg = lane & 3;

    int r0 = blockIdx.y * 128, c0 = blockIdx.x * 128;
    const float* Ab = A + (size_t)r0 * K;
    const __half* Bb = Bm + (size_t)c0 * K;

    float acc[4][4][4];
    #pragma unroll
    for (int mt = 0; mt < 4; mt++)
        #pragma unroll
        for (int nt = 0; nt < 4; nt++)
            #pragma unroll
            for (int e = 0; e < 4; e++) acc[mt][nt][e] = 0.0f;

    float muv[4], rsv[4];
    if (lg) {
        #pragma unroll
        for (int i = 0; i < 4; i++) {
            int r = (tid + i * 256) >> 3;
            combine_stats(psin, r0 + r, muv[i], rsv[i]);
        }
    }

    for (int k0 = 0; k0 < K; k0 += 32) {
        #pragma unroll
        for (int i = 0; i < 4; i++) {
            int idx = tid + i * 256, r = idx >> 3, c4 = idx & 7;
            float4 av = *(const float4*)&Ab[(size_t)r * K + k0 + c4 * 4];
            if (lg) {
                float4 ga = *(const float4*)&lg[k0 + c4 * 4];
                float4 be = *(const float4*)&lb[k0 + c4 * 4];
                float m = muv[i], rr = rsv[i];
                av.x = (av.x - m) * rr * ga.x + be.x;
                av.y = (av.y - m) * rr * ga.y + be.y;
                av.z = (av.z - m) * rr * ga.z + be.z;
                av.w = (av.w - m) * rr * ga.w + be.w;
            }
            unsigned* ap = &As[r * STRH + c4 * 2];
            ap[0] = pack_h2(av.x, av.y);
            ap[1] = pack_h2(av.z, av.w);
        }
        #pragma unroll
        for (int i = 0; i < 2; i++) {
            int idx = tid + i * 256, r = idx >> 2, c8 = idx & 3;
            uint4 bw = *(const uint4*)&Bb[(size_t)r * K + k0 + c8 * 8];
            *(uint4*)&Bs[r * STRH + c8 * 4] = bw;
        }
        __syncthreads();

        #pragma unroll
        for (int kc = 0; kc < 2; kc++) {
            int ko = kc * 8;
            unsigned a[4][4], b[4][2];
            #pragma unroll
            for (int mt = 0; mt < 4; mt++) {
                int row = wm * 64 + mt * 16 + g;
                a[mt][0] = As[row * STRH + ko + tg];
                a[mt][1] = As[(row + 8) * STRH + ko + tg];
                a[mt][2] = As[row * STRH + ko + tg + 4];
                a[mt][3] = As[(row + 8) * STRH + ko + tg + 4];
            }
            #pragma unroll
            for (int nt = 0; nt < 4; nt++) {
                int col = wn * 32 + nt * 8 + g;
                b[nt][0] = Bs[col * STRH + ko + tg];
                b[nt][1] = Bs[col * STRH + ko + tg + 4];
            }
            #pragma unroll
            for (int mt = 0; mt < 4; mt++)
                #pragma unroll
                for (int nt = 0; nt < 4; nt++)
                    mma_f16(acc[mt][nt], a[mt][0], a[mt][1], a[mt][2], a[mt][3],
                            b[nt][0], b[nt][1]);
        }
        __syncthreads();
    }

    #pragma unroll
    for (int mt = 0; mt < 4; mt++) {
        int row = r0 + wm * 64 + mt * 16 + g;
        #pragma unroll
        for (int nt = 0; nt < 4; nt++) {
            int col = c0 + wn * 32 + nt * 8 + 2 * tg;
            float2 bi = *(const float2*)&bias[col];
            #pragma unroll
            for (int half = 0; half < 2; half++) {
                int rr = row + half * 8;
                float x0 = acc[mt][nt][half * 2 + 0] + bi.x;
                float x1 = acc[mt][nt][half * 2 + 1] + bi.y;
                if (mode & 1) { x0 = fmaxf(x0, 0.0f); x1 = fmaxf(x1, 0.0f); }
                *(unsigned*)&C[(size_t)rr * N + col] = pack_h2(x0, x1);
            }
        }
    }
}

// ------------------------- fully fused flash attention -------------------------
// S/R MMAs fp16 (q,k,pkn fp16 inputs); P.V tf32. O written fp16.
// DYNAMIC smem (54784 B): Vs[0,18944) Kh[18944,28160) Ph[28160,46592)
//                         Rs/Ru alias [18944,52736)  msk[52736,54784)
#define KSTRH 36
#define VSTR 37
#define VPANE 2368
#define FLASH_SMEM 54784
__global__ __launch_bounds__(128) void flash_attn(
    const __half* __restrict__ q, const __half* __restrict__ k,
    const float* __restrict__ v, const __half* __restrict__ pkn_l,
    const int* __restrict__ masks, __half* __restrict__ o)
{
    extern __shared__ char sbuf[];
    unsigned* Vs = (unsigned*)sbuf;
    unsigned* Kh = (unsigned*)(sbuf + 18944);
    unsigned* Ph = (unsigned*)(sbuf + 28160);
    float*    Rs = (float*)(sbuf + 18944);
    unsigned* Ru = (unsigned*)(sbuf + 18944);
    int*      msk = (int*)(sbuf + 52736);

    int tid = threadIdx.x;
    int lane = tid & 31, warp = tid >> 5;
    int g = lane >> 2, tg = lane & 3;
    int rl0 = warp * 16 + g, rl1 = rl0 + 8;

    int t0 = blockIdx.x * 64, bh = blockIdx.y;
    int b = bh >> 2, h = bh & 3;
    const __half* qb  = q + ((size_t)(b * T_ + t0)) * D_ + h * DK;
    const __half* kb0 = k + ((size_t)(b * T_)) * D_ + h * DK;
    const float*  vb0 = v + ((size_t)(b * T_)) * D_ + h * DK;

    #pragma unroll
    for (int i = 0; i < 4; i++) msk[tid + i * 128] = masks[b * T_ + tid + i * 128];
    #pragma unroll
    for (int i = 0; i < 4; i++) {
        int idx = tid + i * 128, r = idx >> 3, c8 = idx & 7;
        uint4 w = *(const uint4*)&qb[(size_t)r * D_ + c8 * 8];
        *(uint4*)&Kh[r * KSTRH + c8 * 4] = w;
    }
    __syncthreads();
    unsigned qa[4][4];
    #pragma unroll
    for (int ks = 0; ks < 4; ks++) {
        qa[ks][0] = Kh[rl0 * KSTRH + ks * 8 + tg];
        qa[ks][1] = Kh[rl1 * KSTRH + ks * 8 + tg];
        qa[ks][2] = Kh[rl0 * KSTRH + ks * 8 + tg + 4];
        qa[ks][3] = Kh[rl1 * KSTRH + ks * 8 + tg + 4];
    }
    __syncthreads();

    float accO[8][4];
    #pragma unroll
    for (int nt = 0; nt < 8; nt++)
        #pragma unroll
        for (int e = 0; e < 4; e++) accO[nt][e] = 0.0f;
    float m0 = -FLT_MAX, m1 = -FLT_MAX, l0 = 0.0f, l1 = 0.0f;

    const float scale = 0.125f;

    for (int sc = 0; sc < 8; sc++) {
        int s0 = sc * 64;
        #pragma unroll
        for (int i = 0; i < 4; i++) {
            int idx = tid + i * 128, r = idx >> 3, c8 = idx & 7;
            uint4 w = *(const uint4*)&kb0[(size_t)(s0 + r) * D_ + c8 * 8];
            *(uint4*)&Kh[r * KSTRH + c8 * 4] = w;
        }
        #pragma unroll
        for (int i = 0; i < 8; i++) {
            int idx = tid + i * 128, r = idx >> 4, c4 = idx & 15;
            int half = r >> 5, rsl = r & 31;
            unsigned* vp = &Vs[half * VPANE];
            float4 vv = *(const float4*)&vb0[(size_t)(s0 + r) * D_ + c4 * 4];
            vp[(c4 * 4 + 0) * VSTR + rsl] = f2tf(vv.x);
            vp[(c4 * 4 + 1) * VSTR + rsl] = f2tf(vv.y);
            vp[(c4 * 4 + 2) * VSTR + rsl] = f2tf(vv.z);
            vp[(c4 * 4 + 3) * VSTR + rsl] = f2tf(vv.w);
        }
        const __half* pb = pkn_l + (size_t)(t0 - s0 + 448) * DK;
        #pragma unroll
        for (int i = 0; i < 8; i++) {
            int idx = tid + i * 128, r = idx >> 3, c8 = idx & 7;
            uint4 w;
            if (r < 127) w = *(const uint4*)&pb[(size_t)r * DK + c8 * 8];
            else { w.x = 0u; w.y = 0u; w.z = 0u; w.w = 0u; }
            *(uint4*)&Ph[r * KSTRH + c8 * 4] = w;
        }
        __syncthreads();

        float accS[8][4], accR[16][4];
        #pragma unroll
        for (int nt = 0; nt < 8; nt++)
            #pragma unroll
            for (int e = 0; e < 4; e++) accS[nt][e] = 0.0f;
        #pragma unroll
        for (int nt = 0; nt < 16; nt++)
            #pragma unroll
            for (int e = 0; e < 4; e++) accR[nt][e] = 0.0f;

        #pragma unroll
        for (int ks = 0; ks < 4; ks++) {
            int ko = ks * 8;
            #pragma unroll
            for (int nt = 0; nt < 8; nt++) {
                int col = nt * 8 + g;
                unsigned b0 = Kh[col * KSTRH + ko + tg];
                unsigned b1 = Kh[col * KSTRH + ko + tg + 4];
                mma_f16(accS[nt], qa[ks][0], qa[ks][1], qa[ks][2], qa[ks][3], b0, b1);
            }
            #pragma unroll
            for (int nt = 0; nt < 16; nt++) {
                int col = nt * 8 + g;
                unsigned b0 = Ph[col * KSTRH + ko + tg];
                unsigned b1 = Ph[col * KSTRH + ko + tg + 4];
                mma_f16(accR[nt], qa[ks][0], qa[ks][1], qa[ks][2], qa[ks][3], b0, b1);
            }
        }
        __syncthreads();   // Kh/Ph reads complete before Rs overwrite

        #pragma unroll
        for (int nt = 0; nt < 16; nt++) {
            int col = nt * 8 + 2 * tg;
            Rs[rl0 * 132 + col]     = accR[nt][0];
            Rs[rl0 * 132 + col + 1] = accR[nt][1];
            Rs[rl1 * 132 + col]     = accR[nt][2];
            Rs[rl1 * 132 + col + 1] = accR[nt][3];
        }
        __syncwarp();

        #pragma unroll
        for (int nt = 0; nt < 8; nt++) {
            #pragma unroll
            for (int e = 0; e < 2; e++) {
                int c = nt * 8 + 2 * tg + e;
                float r0 = Rs[rl0 * 132 + (rl0 - c + 63)];
                float r1 = Rs[rl1 * 132 + (rl1 - c + 63)];
                float x0 = (accS[nt][e] + r0) * scale;
                float x1 = (accS[nt][2 + e] + r1) * scale;
                if (msk[s0 + c] == 0) { x0 = -FLT_MAX; x1 = -FLT_MAX; }
                accS[nt][e] = x0;
                accS[nt][2 + e] = x1;
            }
        }
        __syncwarp();

        float cm0 = -FLT_MAX, cm1 = -FLT_MAX;
        #pragma unroll
        for (int nt = 0; nt < 8; nt++) {
            cm0 = fmaxf(cm0, fmaxf(accS[nt][0], accS[nt][1]));
            cm1 = fmaxf(cm1, fmaxf(accS[nt][2], accS[nt][3]));
        }
        cm0 = fmaxf(cm0, __shfl_xor_sync(0xffffffffu, cm0, 1));
        cm0 = fmaxf(cm0, __shfl_xor_sync(0xffffffffu, cm0, 2));
        cm1 = fmaxf(cm1, __shfl_xor_sync(0xffffffffu, cm1, 1));
        cm1 = fmaxf(cm1, __shfl_xor_sync(0xffffffffu, cm1, 2));

        float nm0 = fmaxf(m0, cm0), nm1 = fmaxf(m1, cm1);
        float al0 = __expf(m0 - nm0), al1 = __expf(m1 - nm1);
        float cs0 = 0.0f, cs1 = 0.0f;
        #pragma unroll
        for (int nt = 0; nt < 8; nt++) {
            accS[nt][0] = __expf(accS[nt][0] - nm0);
            accS[nt][1] = __expf(accS[nt][1] - nm0);
            accS[nt][2] = __expf(accS[nt][2] - nm1);
            accS[nt][3] = __expf(accS[nt][3] - nm1);
            cs0 += accS[nt][0] + accS[nt][1];
            cs1 += accS[nt][2] + accS[nt][3];
        }
        cs0 += __shfl_xor_sync(0xffffffffu, cs0, 1);
        cs0 += __shfl_xor_sync(0xffffffffu, cs0, 2);
        cs1 += __shfl_xor_sync(0xffffffffu, cs1, 1);
        cs1 += __shfl_xor_sync(0xffffffffu, cs1, 2);
        l0 = l0 * al0 + cs0;
        l1 = l1 * al1 + cs1;
        m0 = nm0; m1 = nm1;

        #pragma unroll
        for (int nt = 0; nt < 8; nt++) {
            accO[nt][0] *= al0; accO[nt][1] *= al0;
            accO[nt][2] *= al1; accO[nt][3] *= al1;
        }

        #pragma unroll
        for (int nt = 0; nt < 8; nt++) {
            int col = nt * 8 + 2 * tg;
            Ru[rl0 * 132 + col]     = f2tf(accS[nt][0]);
            Ru[rl0 * 132 + col + 1] = f2tf(accS[nt][1]);
            Ru[rl1 * 132 + col]     = f2tf(accS[nt][2]);
            Ru[rl1 * 132 + col + 1] = f2tf(accS[nt][3]);
        }
        __syncwarp();

        #pragma unroll
        for (int kc = 0; kc < 8; kc++) {
            int ko = kc * 8;
            const unsigned* vp = &Vs[(kc >> 2) * VPANE];
            int so = ko & 31;
            unsigned a0 = Ru[rl0 * 132 + ko + tg];
            unsigned a1 = Ru[rl1 * 132 + ko + tg];
            unsigned a2 = Ru[rl0 * 132 + ko + tg + 4];
            unsigned a3 = Ru[rl1 * 132 + ko + tg + 4];
            #pragma unroll
            for (int nt = 0; nt < 8; nt++) {
                int col = nt * 8 + g;
                unsigned b0 = vp[col * VSTR + so + tg];
                unsigned b1 = vp[col * VSTR + so + tg + 4];
                mma_tf32(accO[nt], a0, a1, a2, a3, b0, b1);
            }
        }
        __syncthreads();
    }

    float inv0 = 1.0f / l0, inv1 = 1.0f / l1;
    #pragma unroll
    for (int nt = 0; nt < 8; nt++) {
        int col = nt * 8 + 2 * tg;
        *(unsigned*)&o[((size_t)(b * T_ + t0 + rl0)) * D_ + h * DK + col] =
            pack_h2(accO[nt][0] * inv0, accO[nt][1] * inv0);
        *(unsigned*)&o[((size_t)(b * T_ + t0 + rl1)) * D_ + h * DK + col] =
            pack_h2(accO[nt][2] * inv1, accO[nt][3] * inv1);
    }
}

// ------------------------- host orchestration -------------------------
extern "C" void kernel_launch(void* const* d_in, const int* in_sizes, int n_in,
                              void* d_out, int out_size) {
    const float* xs      = (const float*)d_in[0];
    const int*   masks   = (const int*)  d_in[1];
    const float* emb_w   = (const float*)d_in[2];
    const float* emb_b   = (const float*)d_in[3];
    const float* emb_g   = (const float*)d_in[4];
    const float* emb_bt  = (const float*)d_in[5];
    const float* pe_k    = (const float*)d_in[6];
    const float* Wq      = (const float*)d_in[7];
    const float* bq      = (const float*)d_in[8];
    const float* Wk      = (const float*)d_in[9];
    const float* bk      = (const float*)d_in[10];
    const float* Wv      = (const float*)d_in[11];
    const float* bv      = (const float*)d_in[12];
    const float* Wo      = (const float*)d_in[13];
    const float* bo      = (const float*)d_in[14];
    const float* ln1_g   = (const float*)d_in[15];
    const float* ln1_b   = (const float*)d_in[16];
    const float* ln2_g   = (const float*)d_in[17];
    const float* ln2_b   = (const float*)d_in[18];
    const float* lnk_g   = (const float*)d_in[19];
    const float* lnk_b   = (const float*)d_in[20];
    const float* W1      = (const float*)d_in[21];
    const float* b1      = (const float*)d_in[22];
    const float* W2      = (const float*)d_in[23];
    const float* b2      = (const float*)d_in[24];
    const float* after_g = (const float*)d_in[25];
    const float* after_b = (const float*)d_in[26];
    float* out = (float*)d_out;

    float *x, *y, *v;
    float2* pstat;
    __half *oh, *qh, *kh, *ffh, *pkn, *hemb, *hq, *hk, *hv, *ho, *h1, *h2;
    cudaGetSymbolAddress((void**)&x,     g_x);
    cudaGetSymbolAddress((void**)&y,     g_y);
    cudaGetSymbolAddress((void**)&v,     g_v);
    cudaGetSymbolAddress((void**)&pstat, g_pstat);
    cudaGetSymbolAddress((void**)&oh,    g_oh);
    cudaGetSymbolAddress((void**)&qh,    g_qh);
    cudaGetSymbolAddress((void**)&kh,    g_kh);
    cudaGetSymbolAddress((void**)&ffh,   g_ffh);
    cudaGetSymbolAddress((void**)&pkn,   g_pkn);
    cudaGetSymbolAddress((void**)&hemb,  g_hemb);
    cudaGetSymbolAddress((void**)&hq,    g_hq);
    cudaGetSymbolAddress((void**)&hk,    g_hk);
    cudaGetSymbolAddress((void**)&hv,    g_hv);
    cudaGetSymbolAddress((void**)&ho,    g_ho);
    cudaGetSymbolAddress((void**)&h1,    g_h1);
    cudaGetSymbolAddress((void**)&h2,    g_h2);

    cudaFuncSetAttribute(flash_attn, cudaFuncAttributeMaxDynamicSharedMemorySize, FLASH_SMEM);

    auto conv = [](const float* src, __half* dst, size_t n) {
        int n4 = (int)(n / 4);
        f2h<<<(n4 + 255) / 256, 256>>>(src, dst, n4);
    };
    conv(emb_w, hemb, (size_t)D_ * IDIM);
    conv(Wq, hq, (size_t)L_ * D_ * D_);
    conv(Wk, hk, (size_t)L_ * D_ * D_);
    conv(Wv, hv, (size_t)L_ * D_ * D_);
    conv(Wo, ho, (size_t)L_ * D_ * D_);
    conv(W1, h1, (size_t)L_ * FF_ * D_);
    conv(W2, h2, (size_t)L_ * D_ * FF_);

    dim3 gProj(D_ / 64, BT / 128);       // (4, 32)
    dim3 gQKV(D_ / 64, BT / 128, 3);     // (4, 32, 3)
    dim3 gFF1(FF_ / 128, BT / 128);      // (16, 32)

    // embed: GEMM + bias -> LN(+relu, emits stats); pkn LN (fp16) upfront
    tgemm128_f<<<gProj, 256>>>(xs, hemb, emb_b, nullptr, y, D_, IDIM, 0);
    ln_pkn_all<<<dim3(NPK, L_), 64>>>(pe_k, pkn, lnk_g, lnk_b);
    ln_warp<<<BT / 8, 256>>>(y, x, emb_g, emb_bt, 1, pstat);

    for (int l = 0; l < L_; l++) {
        // QKV with ln1 fused (consumes pstat of x)
        tgemm128_qkv<<<gQKV, 256>>>(x,
            hq + (size_t)l * D_ * D_, hk + (size_t)l * D_ * D_, hv + (size_t)l * D_ * D_,
            bq + l * D_, bk + l * D_, bv + l * D_, qh, kh, v,
            pstat, ln1_g + l * D_, ln1_b + l * D_);

        flash_attn<<<dim3(8, BH), 128, FLASH_SMEM>>>(qh, kh, v,
            pkn + (size_t)l * NPK * DK, masks, oh);

        // Wo + residual -> x, emits stats for FF1
        tgemm128_h<<<gProj, 256>>>(oh, ho + (size_t)l * D_ * D_, bo + l * D_, x, x,
                                   D_, D_, 2, pstat);

        // FF1 with ln2 fused (consumes stats)
        tgemm256<<<gFF1, 256>>>(x, h1 + (size_t)l * FF_ * D_, b1 + l * FF_, ffh,
                                FF_, D_, 1, pstat, ln2_g + l * D_, ln2_b + l * D_);
        // FF2 + residual -> x, emits stats for next layer's QKV
        tgemm128_h<<<gProj, 256>>>(ffh, h2 + (size_t)l * D_ * FF_, b2 + l * D_, x, x,
                                   D_, FF_, 2, pstat);
    }

    ln_warp<<<BT / 8, 256>>>(x, out, after_g, after_b, 0, nullptr);
}

// round 17
// speedup vs baseline: 1.0777x; 1.0478x over previous
#include <cuda_runtime.h>
#include <cuda_fp16.h>
#include <math.h>
#include <float.h>

// Problem constants
#define B_    8
#define T_    512
#define IDIM  1799
#define D_    256
#define H_    4
#define FF_   2048
#define L_    16
#define DK    64
#define BT    (B_*T_)    // 4096
#define BH    (B_*H_)    // 32
#define NPK   1023       // distinct rel-pos rows: t-s+511 in [0,1022]

// ------------------------- scratch (device globals) -------------------------
__device__ float g_x[BT*D_];
__device__ float g_y[BT*D_];
__device__ float2 g_pstat[8*BT];       // 8 partial (sum, sumsq) slots per row
__device__ __half g_oh[BT*D_];
__device__ __half g_qh[BT*D_];
__device__ __half g_kh[BT*D_];
__device__ __half g_vt[(size_t)BH*DK*T_];   // V transposed: [(b*4+h)*64+d][t]
__device__ __half g_ffh[(size_t)BT*FF_];
__device__ __half g_pkn[(size_t)L_*NPK*DK];
// fp16 weights
__device__ __half g_hemb[D_*IDIM];
__device__ __half g_hq[(size_t)L_*D_*D_];
__device__ __half g_hk[(size_t)L_*D_*D_];
__device__ __half g_hv[(size_t)L_*D_*D_];
__device__ __half g_ho[(size_t)L_*D_*D_];
__device__ __half g_h1[(size_t)L_*FF_*D_];
__device__ __half g_h2[(size_t)L_*D_*FF_];

// ------------------------- helpers -------------------------
__device__ __forceinline__ unsigned pack_h2(float lo, float hi) {
    unsigned u;
    asm("cvt.rn.f16x2.f32 %0, %1, %2;" : "=r"(u) : "f"(hi), "f"(lo));
    return u;
}
__device__ __forceinline__ void mma_f16(float c[4],
                                        unsigned a0, unsigned a1, unsigned a2, unsigned a3,
                                        unsigned b0, unsigned b1) {
    asm volatile(
        "mma.sync.aligned.m16n8k16.row.col.f32.f16.f16.f32 "
        "{%0,%1,%2,%3}, {%4,%5,%6,%7}, {%8,%9}, {%0,%1,%2,%3};"
        : "+f"(c[0]), "+f"(c[1]), "+f"(c[2]), "+f"(c[3])
        : "r"(a0), "r"(a1), "r"(a2), "r"(a3), "r"(b0), "r"(b1));
}

// combine 8 partial stats -> (mean, rstd)
__device__ __forceinline__ void combine_stats(const float2* __restrict__ ps, int row,
                                              float& mean, float& rstd) {
    float s = 0.0f, q = 0.0f;
    #pragma unroll
    for (int j = 0; j < 8; j++) {
        float2 p = ps[(size_t)j * BT + row];
        s += p.x; q += p.y;
    }
    mean = s * (1.0f / 256.0f);
    float var = q * (1.0f / 256.0f) - mean * mean;
    rstd = rsqrtf(var + 1e-12f);
}

// ------------------------- fp32 -> fp16 bulk convert -------------------------
__global__ __launch_bounds__(256) void f2h(const float* __restrict__ in,
                                           __half* __restrict__ out, int n4) {
    int i = blockIdx.x * 256 + threadIdx.x;
    if (i < n4) {
        float4 v = *(const float4*)&in[i * 4];
        uint2 o;
        o.x = pack_h2(v.x, v.y);
        o.y = pack_h2(v.z, v.w);
        *(uint2*)&out[i * 4] = o;
    }
}

// ------------------------- block reduction (for pkn LN only) -------------------------
__device__ __forceinline__ float block_sum64(float v) {
    __shared__ float sh[3];
    #pragma unroll
    for (int o = 16; o > 0; o >>= 1) v += __shfl_xor_sync(0xffffffffu, v, o);
    int lane = threadIdx.x & 31, w = threadIdx.x >> 5;
    if (lane == 0) sh[w] = v;
    __syncthreads();
    float out = sh[0] + sh[1];
    __syncthreads();
    return out;
}

// all-layers pkn LN -> fp16: grid (NPK, L), block 64
__global__ void ln_pkn_all(const float* __restrict__ pe_k, __half* __restrict__ pkn,
                           const float* __restrict__ lnk_g, const float* __restrict__ lnk_b) {
    int row = blockIdx.x, l = blockIdx.y;
    float x = pe_k[(size_t)(489 + row) * DK + threadIdx.x];
    float mean = block_sum64(x) / (float)DK;
    float d = x - mean;
    float var = block_sum64(d * d) / (float)DK;
    float y = d * rsqrtf(var + 1e-12f) * lnk_g[l * DK + threadIdx.x] + lnk_b[l * DK + threadIdx.x];
    pkn[((size_t)l * NPK + row) * DK + threadIdx.x] = __float2half_rn(y);
}

// ------------------------- warp-per-row LayerNorm, width 256 -------------------------
__global__ __launch_bounds__(256) void ln_warp(const float* __restrict__ in,
                                               float* __restrict__ out,
                                               const float* __restrict__ g,
                                               const float* __restrict__ bb,
                                               int relu, float2* __restrict__ pstat) {
    int warp = threadIdx.x >> 5, lane = threadIdx.x & 31;
    size_t row = (size_t)blockIdx.x * 8 + warp;
    const float* ip = in + row * D_;
    float4 v0 = *(const float4*)&ip[lane * 4];
    float4 v1 = *(const float4*)&ip[128 + lane * 4];
    float s = v0.x + v0.y + v0.z + v0.w + v1.x + v1.y + v1.z + v1.w;
    #pragma unroll
    for (int o = 16; o > 0; o >>= 1) s += __shfl_xor_sync(0xffffffffu, s, o);
    float mean = s * (1.0f / 256.0f);
    float d0x = v0.x - mean, d0y = v0.y - mean, d0z = v0.z - mean, d0w = v0.w - mean;
    float d1x = v1.x - mean, d1y = v1.y - mean, d1z = v1.z - mean, d1w = v1.w - mean;
    float vs = d0x*d0x + d0y*d0y + d0z*d0z + d0w*d0w + d1x*d1x + d1y*d1y + d1z*d1z + d1w*d1w;
    #pragma unroll
    for (int o = 16; o > 0; o >>= 1) vs += __shfl_xor_sync(0xffffffffu, vs, o);
    float rstd = rsqrtf(vs * (1.0f / 256.0f) + 1e-12f);
    float4 g0 = *(const float4*)&g[lane * 4];
    float4 g1 = *(const float4*)&g[128 + lane * 4];
    float4 b0 = *(const float4*)&bb[lane * 4];
    float4 b1 = *(const float4*)&bb[128 + lane * 4];
    float4 o0, o1;
    o0.x = d0x * rstd * g0.x + b0.x;  o0.y = d0y * rstd * g0.y + b0.y;
    o0.z = d0z * rstd * g0.z + b0.z;  o0.w = d0w * rstd * g0.w + b0.w;
    o1.x = d1x * rstd * g1.x + b1.x;  o1.y = d1y * rstd * g1.y + b1.y;
    o1.z = d1z * rstd * g1.z + b1.z;  o1.w = d1w * rstd * g1.w + b1.w;
    if (relu) {
        o0.x = fmaxf(o0.x, 0.f); o0.y = fmaxf(o0.y, 0.f); o0.z = fmaxf(o0.z, 0.f); o0.w = fmaxf(o0.w, 0.f);
        o1.x = fmaxf(o1.x, 0.f); o1.y = fmaxf(o1.y, 0.f); o1.z = fmaxf(o1.z, 0.f); o1.w = fmaxf(o1.w, 0.f);
    }
    float* op = out + row * D_;
    *(float4*)&op[lane * 4] = o0;
    *(float4*)&op[128 + lane * 4] = o1;

    if (pstat) {
        float ss = o0.x + o0.y + o0.z + o0.w + o1.x + o1.y + o1.z + o1.w;
        float qq = o0.x*o0.x + o0.y*o0.y + o0.z*o0.z + o0.w*o0.w
                 + o1.x*o1.x + o1.y*o1.y + o1.z*o1.z + o1.w*o1.w;
        #pragma unroll
        for (int o = 16; o > 0; o >>= 1) {
            ss += __shfl_xor_sync(0xffffffffu, ss, o);
            qq += __shfl_xor_sync(0xffffffffu, qq, o);
        }
        if (lane == 0) {
            pstat[row] = make_float2(ss, qq);
            #pragma unroll
            for (int j = 1; j < 8; j++)
                pstat[(size_t)j * BT + row] = make_float2(0.0f, 0.0f);
        }
    }
}

// ------------------------- FP16 GEMM body, BM=128 BN=64 BK=32 -------------------------
// B always fp16. A fp32 (+opt fused LN via partial stats) or fp16 (template AH).
// c_half: 0 = fp32 row-major (+opt residual), 1 = fp16 row-major, 2 = fp16 transposed [col][t].
// Optionally emits partial row stats of C (psout).
#define STRH 20
template<bool AH>
__device__ __forceinline__ void tg128_body(
    const void* __restrict__ Ap, const __half* __restrict__ Bm,
    const float* __restrict__ bias, const float* __restrict__ R,
    void* __restrict__ Cp, int N, int K, int mode, int c_half, int r0, int c0,
    const float2* __restrict__ psin,
    const float* __restrict__ lg, const float* __restrict__ lb,
    float2* __restrict__ psout, int pslot)
{
    __shared__ unsigned As[128 * STRH];
    __shared__ unsigned Bs[64 * STRH];

    int tid = threadIdx.x;
    int lane = tid & 31, warp = tid >> 5;
    int wm = warp >> 1, wn = warp & 1;
    int g = lane >> 2, tg = lane & 3;

    const float*  Af = AH ? nullptr : (const float*)Ap + (size_t)r0 * K;
    const __half* Ah = AH ? (const __half*)Ap + (size_t)r0 * K : nullptr;
    const __half* Bb = Bm + (size_t)c0 * K;

    float acc[2][4][4];
    #pragma unroll
    for (int mt = 0; mt < 2; mt++)
        #pragma unroll
        for (int nt = 0; nt < 4; nt++)
            #pragma unroll
            for (int e = 0; e < 4; e++) acc[mt][nt][e] = 0.0f;

    float muv[4], rsv[4];
    if (!AH && lg) {
        #pragma unroll
        for (int i = 0; i < 4; i++) {
            int r = (tid + i * 256) >> 3;
            combine_stats(psin, r0 + r, muv[i], rsv[i]);
        }
    }

    auto do_mma = [&]() {
        #pragma unroll
        for (int kc = 0; kc < 2; kc++) {
            int ko = kc * 8;
            unsigned a[2][4], b[4][2];
            #pragma unroll
            for (int mt = 0; mt < 2; mt++) {
                int row = wm * 32 + mt * 16 + g;
                a[mt][0] = As[row * STRH + ko + tg];
                a[mt][1] = As[(row + 8) * STRH + ko + tg];
                a[mt][2] = As[row * STRH + ko + tg + 4];
                a[mt][3] = As[(row + 8) * STRH + ko + tg + 4];
            }
            #pragma unroll
            for (int nt = 0; nt < 4; nt++) {
                int col = wn * 32 + nt * 8 + g;
                b[nt][0] = Bs[col * STRH + ko + tg];
                b[nt][1] = Bs[col * STRH + ko + tg + 4];
            }
            #pragma unroll
            for (int mt = 0; mt < 2; mt++)
                #pragma unroll
                for (int nt = 0; nt < 4; nt++)
                    mma_f16(acc[mt][nt], a[mt][0], a[mt][1], a[mt][2], a[mt][3],
                            b[nt][0], b[nt][1]);
        }
    };

    if ((K & 31) == 0) {
        int nch = K >> 5;
        int br = tid >> 2, bc8 = tid & 3;
        uint4 pbh = *(const uint4*)&Bb[(size_t)br * K + bc8 * 8];

        if (AH) {
            uint4 pah[2];
            #pragma unroll
            for (int i = 0; i < 2; i++) {
                int idx = tid + i * 256, r = idx >> 2, c8 = idx & 3;
                pah[i] = *(const uint4*)&Ah[(size_t)r * K + c8 * 8];
            }
            #pragma unroll
            for (int i = 0; i < 2; i++) {
                int idx = tid + i * 256, r = idx >> 2, c8 = idx & 3;
                *(uint4*)&As[r * STRH + c8 * 4] = pah[i];
            }
            *(uint4*)&Bs[br * STRH + bc8 * 4] = pbh;
            __syncthreads();
            for (int ch = 0; ch < nch; ch++) {
                bool more = (ch + 1 < nch);
                int k1 = (ch + 1) << 5;
                if (more) {
                    #pragma unroll
                    for (int i = 0; i < 2; i++) {
                        int idx = tid + i * 256, r = idx >> 2, c8 = idx & 3;
                        pah[i] = *(const uint4*)&Ah[(size_t)r * K + k1 + c8 * 8];
                    }
                    pbh = *(const uint4*)&Bb[(size_t)br * K + k1 + bc8 * 8];
                }
                do_mma();
                if (more) {
                    __syncthreads();
                    #pragma unroll
                    for (int i = 0; i < 2; i++) {
                        int idx = tid + i * 256, r = idx >> 2, c8 = idx & 3;
                        *(uint4*)&As[r * STRH + c8 * 4] = pah[i];
                    }
                    *(uint4*)&Bs[br * STRH + bc8 * 4] = pbh;
                    __syncthreads();
                }
            }
        } else {
            float4 pa[4];
            #pragma unroll
            for (int i = 0; i < 4; i++) {
                int idx = tid + i * 256, r = idx >> 3, c4 = idx & 7;
                pa[i] = *(const float4*)&Af[(size_t)r * K + c4 * 4];
            }
            auto store_a = [&](float4 av, int i, int kbase) {
                int idx = tid + i * 256, r = idx >> 3, c4 = idx & 7;
                if (lg) {
                    float4 ga = *(const float4*)&lg[kbase + c4 * 4];
                    float4 be = *(const float4*)&lb[kbase + c4 * 4];
                    float m = muv[i], rr = rsv[i];
                    av.x = (av.x - m) * rr * ga.x + be.x;
                    av.y = (av.y - m) * rr * ga.y + be.y;
                    av.z = (av.z - m) * rr * ga.z + be.z;
                    av.w = (av.w - m) * rr * ga.w + be.w;
                }
                unsigned* ap = &As[r * STRH + c4 * 2];
                ap[0] = pack_h2(av.x, av.y);
                ap[1] = pack_h2(av.z, av.w);
            };
            #pragma unroll
            for (int i = 0; i < 4; i++) store_a(pa[i], i, 0);
            *(uint4*)&Bs[br * STRH + bc8 * 4] = pbh;
            __syncthreads();
            for (int ch = 0; ch < nch; ch++) {
                bool more = (ch + 1 < nch);
                int k1 = (ch + 1) << 5;
                if (more) {
                    #pragma unroll
                    for (int i = 0; i < 4; i++) {
                        int idx = tid + i * 256, r = idx >> 3, c4 = idx & 7;
                        pa[i] = *(const float4*)&Af[(size_t)r * K + k1 + c4 * 4];
                    }
                    pbh = *(const uint4*)&Bb[(size_t)br * K + k1 + bc8 * 8];
                }
                do_mma();
                if (more) {
                    __syncthreads();
                    #pragma unroll
                    for (int i = 0; i < 4; i++) store_a(pa[i], i, k1);
                    *(uint4*)&Bs[br * STRH + bc8 * 4] = pbh;
                    __syncthreads();
                }
            }
        }
    } else {
        // guarded scalar path (embed GEMM, K=1799): A fp32, B fp16
        for (int k0 = 0; k0 < K; k0 += 32) {
            #pragma unroll
            for (int i = 0; i < 8; i++) {
                int idx = tid + i * 256, r = idx >> 4, c2 = idx & 15;
                int kk = k0 + c2 * 2;
                float f0 = (kk < K)     ? Af[(size_t)r * K + kk]     : 0.0f;
                float f1 = (kk + 1 < K) ? Af[(size_t)r * K + kk + 1] : 0.0f;
                As[r * STRH + c2] = pack_h2(f0, f1);
            }
            #pragma unroll
            for (int i = 0; i < 4; i++) {
                int idx = tid + i * 256, r = idx >> 4, c2 = idx & 15;
                int kk = k0 + c2 * 2;
                float f0 = (kk < K)     ? __half2float(Bb[(size_t)r * K + kk])     : 0.0f;
                float f1 = (kk + 1 < K) ? __half2float(Bb[(size_t)r * K + kk + 1]) : 0.0f;
                Bs[r * STRH + c2] = pack_h2(f0, f1);
            }
            __syncthreads();
            do_mma();
            __syncthreads();
        }
    }

    float ps_[2][2], pq_[2][2];
    #pragma unroll
    for (int mt = 0; mt < 2; mt++)
        #pragma unroll
        for (int hf = 0; hf < 2; hf++) { ps_[mt][hf] = 0.0f; pq_[mt][hf] = 0.0f; }

    #pragma unroll
    for (int mt = 0; mt < 2; mt++) {
        int row = r0 + wm * 32 + mt * 16 + g;
        #pragma unroll
        for (int nt = 0; nt < 4; nt++) {
            int col = c0 + wn * 32 + nt * 8 + 2 * tg;
            float2 bi = *(const float2*)&bias[col];
            #pragma unroll
            for (int half = 0; half < 2; half++) {
                int rr = row + half * 8;
                float x0 = acc[mt][nt][half * 2 + 0] + bi.x;
                float x1 = acc[mt][nt][half * 2 + 1] + bi.y;
                if (mode & 2) {
                    float2 rv = *(const float2*)&R[(size_t)rr * N + col];
                    x0 += rv.x; x1 += rv.y;
                }
                if (mode & 1) { x0 = fmaxf(x0, 0.0f); x1 = fmaxf(x1, 0.0f); }
                if (psout) {
                    ps_[mt][half] += x0 + x1;
                    pq_[mt][half] += x0 * x0 + x1 * x1;
                }
                if (c_half == 1) {
                    *(unsigned*)&((__half*)Cp)[(size_t)rr * N + col] = pack_h2(x0, x1);
                } else if (c_half == 2) {
                    // transposed fp16: vT[(b*256+col)*512 + t]
                    int bb2 = rr >> 9, tt = rr & 511;
                    __half* vt = (__half*)Cp;
                    vt[((size_t)(bb2 * 256 + col)) * 512 + tt]     = __float2half_rn(x0);
                    vt[((size_t)(bb2 * 256 + col + 1)) * 512 + tt] = __float2half_rn(x1);
                } else {
                    float2 o2 = {x0, x1};
                    *(float2*)&((float*)Cp)[(size_t)rr * N + col] = o2;
                }
            }
        }
    }

    if (psout) {
        #pragma unroll
        for (int mt = 0; mt < 2; mt++)
            #pragma unroll
            for (int hf = 0; hf < 2; hf++) {
                float s = ps_[mt][hf], q = pq_[mt][hf];
                s += __shfl_xor_sync(0xffffffffu, s, 1);
                s += __shfl_xor_sync(0xffffffffu, s, 2);
                q += __shfl_xor_sync(0xffffffffu, q, 1);
                q += __shfl_xor_sync(0xffffffffu, q, 2);
                if (tg == 0) {
                    int row = r0 + wm * 32 + mt * 16 + g + hf * 8;
                    psout[(size_t)(pslot + wn) * BT + row] = make_float2(s, q);
                }
            }
    }
}

__global__ __launch_bounds__(256) void tgemm128_f(
    const float* __restrict__ A, const __half* __restrict__ Bm,
    const float* __restrict__ bias, const float* __restrict__ R,
    float* __restrict__ C, int N, int K, int mode)
{
    tg128_body<false>(A, Bm, bias, R, C, N, K, mode, 0,
                      blockIdx.y * 128, blockIdx.x * 64,
                      nullptr, nullptr, nullptr, nullptr, 0);
}

// fp16-A GEMM; optionally emits partial row stats of C
__global__ __launch_bounds__(256) void tgemm128_h(
    const __half* __restrict__ A, const __half* __restrict__ Bm,
    const float* __restrict__ bias, const float* __restrict__ R,
    float* __restrict__ C, int N, int K, int mode, float2* __restrict__ psout)
{
    tg128_body<true>(A, Bm, bias, R, C, N, K, mode, 0,
                     blockIdx.y * 128, blockIdx.x * 64,
                     nullptr, nullptr, nullptr, psout, blockIdx.x * 2);
}

// batched Q/K/V with LN-from-partial-stats: z=0 -> q fp16, z=1 -> k fp16, z=2 -> vT fp16
__global__ __launch_bounds__(256) void tgemm128_qkv(
    const float* __restrict__ A,
    const __half* __restrict__ Wq, const __half* __restrict__ Wk, const __half* __restrict__ Wv,
    const float* __restrict__ bq, const float* __restrict__ bk, const float* __restrict__ bv,
    __half* __restrict__ qh, __half* __restrict__ kh, __half* __restrict__ vt,
    const float2* __restrict__ psin,
    const float* __restrict__ lg, const float* __restrict__ lb)
{
    const __half* W; const float* bi; void* C; int ch;
    if (blockIdx.z == 0)      { W = Wq; bi = bq; C = qh; ch = 1; }
    else if (blockIdx.z == 1) { W = Wk; bi = bk; C = kh; ch = 1; }
    else                      { W = Wv; bi = bv; C = vt; ch = 2; }
    tg128_body<false>(A, W, bi, nullptr, C, D_, D_, 0, ch,
                      blockIdx.y * 128, blockIdx.x * 64, psin, lg, lb, nullptr, 0);
}

// ------------------------- FP16 GEMM, BM=128 BN=128 BK=32 (FF1, fp16 out) -----------------
__global__ __launch_bounds__(256) void tgemm256(
    const float* __restrict__ A, const __half* __restrict__ Bm,
    const float* __restrict__ bias, __half* __restrict__ C,
    int N, int K, int mode,
    const float2* __restrict__ psin,
    const float* __restrict__ lg, const float* __restrict__ lb)
{
    __shared__ unsigned As[128 * STRH];
    __shared__ unsigned Bs[128 * STRH];

    int tid = threadIdx.x;
    int lane = tid & 31, warp = tid >> 5;
    int wm = warp >> 2, wn = warp & 3;
    int g = lane >> 2, tg = lane & 3;

    int r0 = blockIdx.y * 128, c0 = blockIdx.x * 128;
    const float* Ab = A + (size_t)r0 * K;
    const __half* Bb = Bm + (size_t)c0 * K;

    float acc[4][4][4];
    #pragma unroll
    for (int mt = 0; mt < 4; mt++)
        #pragma unroll
        for (int nt = 0; nt < 4; nt++)
            #pragma unroll
            for (int e = 0; e < 4; e++) acc[mt][nt][e] = 0.0f;

    float muv[4], rsv[4];
    if (lg) {
        #pragma unroll
        for (int i = 0; i < 4; i++) {
            int r = (tid + i * 256) >> 3;
            combine_stats(psin, r0 + r, muv[i], rsv[i]);
        }
    }

    for (int k0 = 0; k0 < K; k0 += 32) {
        #pragma unroll
        for (int i = 0; i < 4; i++) {
            int idx = tid + i * 256, r = idx >> 3, c4 = idx & 7;
            float4 av = *(const float4*)&Ab[(size_t)r * K + k0 + c4 * 4];
            if (lg) {
                float4 ga = *(const float4*)&lg[k0 + c4 * 4];
                float4 be = *(const float4*)&lb[k0 + c4 * 4];
                float m = muv[i], rr = rsv[i];
                av.x = (av.x - m) * rr * ga.x + be.x;
                av.y = (av.y - m) * rr * ga.y + be.y;
                av.z = (av.z - m) * rr * ga.z + be.z;
                av.w = (av.w - m) * rr * ga.w + be.w;
            }
            unsigned* ap = &As[r * STRH + c4 * 2];
            ap[0] = pack_h2(av.x, av.y);
            ap[1] = pack_h2(av.z, av.w);
        }
        #pragma unroll
        for (int i = 0; i < 2; i++) {
            int idx = tid + i * 256, r = idx >> 2, c8 = idx & 3;
            uint4 bw = *(const uint4*)&Bb[(size_t)r * K + k0 + c8 * 8];
            *(uint4*)&Bs[r * STRH + c8 * 4] = bw;
        }
        __syncthreads();

        #pragma unroll
        for (int kc = 0; kc < 2; kc++) {
            int ko = kc * 8;
            unsigned a[4][4], b[4][2];
            #pragma unroll
            for (int mt = 0; mt < 4; mt++) {
                int row = wm * 64 + mt * 16 + g;
                a[mt][0] = As[row * STRH + ko + tg];
                a[mt][1] = As[(row + 8) * STRH + ko + tg];
                a[mt][2] = As[row * STRH + ko + tg + 4];
                a[mt][3] = As[(row + 8) * STRH + ko + tg + 4];
            }
            #pragma unroll
            for (int nt = 0; nt < 4; nt++) {
                int col = wn * 32 + nt * 8 + g;
                b[nt][0] = Bs[col * STRH + ko + tg];
                b[nt][1] = Bs[col * STRH + ko + tg + 4];
            }
            #pragma unroll
            for (int mt = 0; mt < 4; mt++)
                #pragma unroll
                for (int nt = 0; nt < 4; nt++)
                    mma_f16(acc[mt][nt], a[mt][0], a[mt][1], a[mt][2], a[mt][3],
                            b[nt][0], b[nt][1]);
        }
        __syncthreads();
    }

    #pragma unroll
    for (int mt = 0; mt < 4; mt++) {
        int row = r0 + wm * 64 + mt * 16 + g;
        #pragma unroll
        for (int nt = 0; nt < 4; nt++) {
            int col = c0 + wn * 32 + nt * 8 + 2 * tg;
            float2 bi = *(const float2*)&bias[col];
            #pragma unroll
            for (int half = 0; half < 2; half++) {
                int rr = row + half * 8;
                float x0 = acc[mt][nt][half * 2 + 0] + bi.x;
                float x1 = acc[mt][nt][half * 2 + 1] + bi.y;
                if (mode & 1) { x0 = fmaxf(x0, 0.0f); x1 = fmaxf(x1, 0.0f); }
                *(unsigned*)&C[(size_t)rr * N + col] = pack_h2(x0, x1);
            }
        }
    }
}

// ------------------------- fully fused flash attention (all-fp16 MMA) -------------------------
// S/R MMAs fp16; P.V fp16 (V pre-transposed in gmem). O written fp16.
// DYNAMIC smem (54528 B):
//   Vh  [0, 9472)       : 64 d-rows x VSTRH=37 h2 words (s=64)
//   Ruh [9472, 18688)   : 64 t-rows x 36 h2 words (probs)
//   Kh  [18688, 27904)  : 64 rows x KSTRH=36 h2 words
//   Ph  [27904, 46336)  : 128 rows x KSTRH=36 h2 words
//   Rs alias [18688, 52480) : 64 rows x 132 fp32 (over Kh+Ph, NOT Vh/Ruh)
//   msk [52480, 54528)
#define KSTRH 36
#define VSTRH 37
#define FLASH_SMEM 54528
__global__ __launch_bounds__(128) void flash_attn(
    const __half* __restrict__ q, const __half* __restrict__ k,
    const __half* __restrict__ vt, const __half* __restrict__ pkn_l,
    const int* __restrict__ masks, __half* __restrict__ o)
{
    extern __shared__ char sbuf[];
    unsigned* Vh  = (unsigned*)sbuf;
    unsigned* Ruh = (unsigned*)(sbuf + 9472);
    unsigned* Kh  = (unsigned*)(sbuf + 18688);
    unsigned* Ph  = (unsigned*)(sbuf + 27904);
    float*    Rs  = (float*)(sbuf + 18688);
    int*      msk = (int*)(sbuf + 52480);

    int tid = threadIdx.x;
    int lane = tid & 31, warp = tid >> 5;
    int g = lane >> 2, tg = lane & 3;
    int rl0 = warp * 16 + g, rl1 = rl0 + 8;

    int t0 = blockIdx.x * 64, bh = blockIdx.y;
    int b = bh >> 2, h = bh & 3;
    const __half* qb  = q + ((size_t)(b * T_ + t0)) * D_ + h * DK;
    const __half* kb0 = k + ((size_t)(b * T_)) * D_ + h * DK;
    const __half* vb0 = vt + (size_t)bh * DK * T_;

    #pragma unroll
    for (int i = 0; i < 4; i++) msk[tid + i * 128] = masks[b * T_ + tid + i * 128];
    #pragma unroll
    for (int i = 0; i < 4; i++) {
        int idx = tid + i * 128, r = idx >> 3, c8 = idx & 7;
        uint4 w = *(const uint4*)&qb[(size_t)r * D_ + c8 * 8];
        *(uint4*)&Kh[r * KSTRH + c8 * 4] = w;
    }
    __syncthreads();
    unsigned qa[4][4];
    #pragma unroll
    for (int ks = 0; ks < 4; ks++) {
        qa[ks][0] = Kh[rl0 * KSTRH + ks * 8 + tg];
        qa[ks][1] = Kh[rl1 * KSTRH + ks * 8 + tg];
        qa[ks][2] = Kh[rl0 * KSTRH + ks * 8 + tg + 4];
        qa[ks][3] = Kh[rl1 * KSTRH + ks * 8 + tg + 4];
    }
    __syncthreads();

    float accO[8][4];
    #pragma unroll
    for (int nt = 0; nt < 8; nt++)
        #pragma unroll
        for (int e = 0; e < 4; e++) accO[nt][e] = 0.0f;
    float m0 = -FLT_MAX, m1 = -FLT_MAX, l0 = 0.0f, l1 = 0.0f;

    const float scale = 0.125f;

    for (int sc = 0; sc < 8; sc++) {
        int s0 = sc * 64;
        // ---- stage K (fp16 copy) ----
        #pragma unroll
        for (int i = 0; i < 4; i++) {
            int idx = tid + i * 128, r = idx >> 3, c8 = idx & 7;
            uint4 w = *(const uint4*)&kb0[(size_t)(s0 + r) * D_ + c8 * 8];
            *(uint4*)&Kh[r * KSTRH + c8 * 4] = w;
        }
        // ---- stage V^T (fp16 copy; word stores, rows 148B apart) ----
        #pragma unroll
        for (int i = 0; i < 4; i++) {
            int idx = tid + i * 128, d = idx >> 3, c8 = idx & 7;
            uint4 w = *(const uint4*)&vb0[(size_t)d * T_ + s0 + c8 * 8];
            unsigned* vp = &Vh[d * VSTRH + c8 * 4];
            vp[0] = w.x; vp[1] = w.y; vp[2] = w.z; vp[3] = w.w;
        }
        // ---- stage P (fp16 copy; 127 rows + zero row) ----
        const __half* pb = pkn_l + (size_t)(t0 - s0 + 448) * DK;
        #pragma unroll
        for (int i = 0; i < 8; i++) {
            int idx = tid + i * 128, r = idx >> 3, c8 = idx & 7;
            uint4 w;
            if (r < 127) w = *(const uint4*)&pb[(size_t)r * DK + c8 * 8];
            else { w.x = 0u; w.y = 0u; w.z = 0u; w.w = 0u; }
            *(uint4*)&Ph[r * KSTRH + c8 * 4] = w;
        }
        __syncthreads();

        // ---- S and R MMAs (fp16) ----
        float accS[8][4], accR[16][4];
        #pragma unroll
        for (int nt = 0; nt < 8; nt++)
            #pragma unroll
            for (int e = 0; e < 4; e++) accS[nt][e] = 0.0f;
        #pragma unroll
        for (int nt = 0; nt < 16; nt++)
            #pragma unroll
            for (int e = 0; e < 4; e++) accR[nt][e] = 0.0f;

        #pragma unroll
        for (int ks = 0; ks < 4; ks++) {
            int ko = ks * 8;
            #pragma unroll
            for (int nt = 0; nt < 8; nt++) {
                int col = nt * 8 + g;
                unsigned b0 = Kh[col * KSTRH + ko + tg];
                unsigned b1 = Kh[col * KSTRH + ko + tg + 4];
                mma_f16(accS[nt], qa[ks][0], qa[ks][1], qa[ks][2], qa[ks][3], b0, b1);
            }
            #pragma unroll
            for (int nt = 0; nt < 16; nt++) {
                int col = nt * 8 + g;
                unsigned b0 = Ph[col * KSTRH + ko + tg];
                unsigned b1 = Ph[col * KSTRH + ko + tg + 4];
                mma_f16(accR[nt], qa[ks][0], qa[ks][1], qa[ks][2], qa[ks][3], b0, b1);
            }
        }
        __syncthreads();   // Kh/Ph reads complete before Rs overwrite

        // ---- spill R (warp-private rows; stride 132 conflict-free) ----
        #pragma unroll
        for (int nt = 0; nt < 16; nt++) {
            int col = nt * 8 + 2 * tg;
            Rs[rl0 * 132 + col]     = accR[nt][0];
            Rs[rl0 * 132 + col + 1] = accR[nt][1];
            Rs[rl1 * 132 + col]     = accR[nt][2];
            Rs[rl1 * 132 + col + 1] = accR[nt][3];
        }
        __syncwarp();

        // ---- gather diagonals, scale + mask ----
        #pragma unroll
        for (int nt = 0; nt < 8; nt++) {
            #pragma unroll
            for (int e = 0; e < 2; e++) {
                int c = nt * 8 + 2 * tg + e;
                float r0 = Rs[rl0 * 132 + (rl0 - c + 63)];
                float r1 = Rs[rl1 * 132 + (rl1 - c + 63)];
                float x0 = (accS[nt][e] + r0) * scale;
                float x1 = (accS[nt][2 + e] + r1) * scale;
                if (msk[s0 + c] == 0) { x0 = -FLT_MAX; x1 = -FLT_MAX; }
                accS[nt][e] = x0;
                accS[nt][2 + e] = x1;
            }
        }
        __syncwarp();

        // ---- online softmax (quad-local) ----
        float cm0 = -FLT_MAX, cm1 = -FLT_MAX;
        #pragma unroll
        for (int nt = 0; nt < 8; nt++) {
            cm0 = fmaxf(cm0, fmaxf(accS[nt][0], accS[nt][1]));
            cm1 = fmaxf(cm1, fmaxf(accS[nt][2], accS[nt][3]));
        }
        cm0 = fmaxf(cm0, __shfl_xor_sync(0xffffffffu, cm0, 1));
        cm0 = fmaxf(cm0, __shfl_xor_sync(0xffffffffu, cm0, 2));
        cm1 = fmaxf(cm1, __shfl_xor_sync(0xffffffffu, cm1, 1));
        cm1 = fmaxf(cm1, __shfl_xor_sync(0xffffffffu, cm1, 2));

        float nm0 = fmaxf(m0, cm0), nm1 = fmaxf(m1, cm1);
        float al0 = __expf(m0 - nm0), al1 = __expf(m1 - nm1);
        float cs0 = 0.0f, cs1 = 0.0f;
        #pragma unroll
        for (int nt = 0; nt < 8; nt++) {
            accS[nt][0] = __expf(accS[nt][0] - nm0);
            accS[nt][1] = __expf(accS[nt][1] - nm0);
            accS[nt][2] = __expf(accS[nt][2] - nm1);
            accS[nt][3] = __expf(accS[nt][3] - nm1);
            cs0 += accS[nt][0] + accS[nt][1];
            cs1 += accS[nt][2] + accS[nt][3];
        }
        cs0 += __shfl_xor_sync(0xffffffffu, cs0, 1);
        cs0 += __shfl_xor_sync(0xffffffffu, cs0, 2);
        cs1 += __shfl_xor_sync(0xffffffffu, cs1, 1);
        cs1 += __shfl_xor_sync(0xffffffffu, cs1, 2);
        l0 = l0 * al0 + cs0;
        l1 = l1 * al1 + cs1;
        m0 = nm0; m1 = nm1;

        #pragma unroll
        for (int nt = 0; nt < 8; nt++) {
            accO[nt][0] *= al0; accO[nt][1] *= al0;
            accO[nt][2] *= al1; accO[nt][3] *= al1;
        }

        // ---- probs -> fp16 pane (warp-private; word nt*4+tg holds s = nt*8+2tg, +1) ----
        #pragma unroll
        for (int nt = 0; nt < 8; nt++) {
            Ruh[rl0 * 36 + nt * 4 + tg] = pack_h2(accS[nt][0], accS[nt][1]);
            Ruh[rl1 * 36 + nt * 4 + tg] = pack_h2(accS[nt][2], accS[nt][3]);
        }
        __syncwarp();

        // ---- O += P @ V (fp16, 4 k16 steps) ----
        #pragma unroll
        for (int ks = 0; ks < 4; ks++) {
            int ko = ks * 8;
            unsigned a0 = Ruh[rl0 * 36 + ko + tg];
            unsigned a1 = Ruh[rl1 * 36 + ko + tg];
            unsigned a2 = Ruh[rl0 * 36 + ko + tg + 4];
            unsigned a3 = Ruh[rl1 * 36 + ko + tg + 4];
            #pragma unroll
            for (int nt = 0; nt < 8; nt++) {
                int col = nt * 8 + g;
                unsigned b0 = Vh[col * VSTRH + ko + tg];
                unsigned b1 = Vh[col * VSTRH + ko + tg + 4];
                mma_f16(accO[nt], a0, a1, a2, a3, b0, b1);
            }
        }
        __syncthreads();   // Vh/Ruh/Rs consumption complete before next stage
    }

    float inv0 = 1.0f / l0, inv1 = 1.0f / l1;
    #pragma unroll
    for (int nt = 0; nt < 8; nt++) {
        int col = nt * 8 + 2 * tg;
        *(unsigned*)&o[((size_t)(b * T_ + t0 + rl0)) * D_ + h * DK + col] =
            pack_h2(accO[nt][0] * inv0, accO[nt][1] * inv0);
        *(unsigned*)&o[((size_t)(b * T_ + t0 + rl1)) * D_ + h * DK + col] =
            pack_h2(accO[nt][2] * inv1, accO[nt][3] * inv1);
    }
}

// ------------------------- host orchestration -------------------------
extern "C" void kernel_launch(void* const* d_in, const int* in_sizes, int n_in,
                              void* d_out, int out_size) {
    const float* xs      = (const float*)d_in[0];
    const int*   masks   = (const int*)  d_in[1];
    const float* emb_w   = (const float*)d_in[2];
    const float* emb_b   = (const float*)d_in[3];
    const float* emb_g   = (const float*)d_in[4];
    const float* emb_bt  = (const float*)d_in[5];
    const float* pe_k    = (const float*)d_in[6];
    const float* Wq      = (const float*)d_in[7];
    const float* bq      = (const float*)d_in[8];
    const float* Wk      = (const float*)d_in[9];
    const float* bk      = (const float*)d_in[10];
    const float* Wv      = (const float*)d_in[11];
    const float* bv      = (const float*)d_in[12];
    const float* Wo      = (const float*)d_in[13];
    const float* bo      = (const float*)d_in[14];
    const float* ln1_g   = (const float*)d_in[15];
    const float* ln1_b   = (const float*)d_in[16];
    const float* ln2_g   = (const float*)d_in[17];
    const float* ln2_b   = (const float*)d_in[18];
    const float* lnk_g   = (const float*)d_in[19];
    const float* lnk_b   = (const float*)d_in[20];
    const float* W1      = (const float*)d_in[21];
    const float* b1      = (const float*)d_in[22];
    const float* W2      = (const float*)d_in[23];
    const float* b2      = (const float*)d_in[24];
    const float* after_g = (const float*)d_in[25];
    const float* after_b = (const float*)d_in[26];
    float* out = (float*)d_out;

    float *x, *y;
    float2* pstat;
    __half *oh, *qh, *kh, *vt, *ffh, *pkn, *hemb, *hq, *hk, *hv, *ho, *h1, *h2;
    cudaGetSymbolAddress((void**)&x,     g_x);
    cudaGetSymbolAddress((void**)&y,     g_y);
    cudaGetSymbolAddress((void**)&pstat, g_pstat);
    cudaGetSymbolAddress((void**)&oh,    g_oh);
    cudaGetSymbolAddress((void**)&qh,    g_qh);
    cudaGetSymbolAddress((void**)&kh,    g_kh);
    cudaGetSymbolAddress((void**)&vt,    g_vt);
    cudaGetSymbolAddress((void**)&ffh,   g_ffh);
    cudaGetSymbolAddress((void**)&pkn,   g_pkn);
    cudaGetSymbolAddress((void**)&hemb,  g_hemb);
    cudaGetSymbolAddress((void**)&hq,    g_hq);
    cudaGetSymbolAddress((void**)&hk,    g_hk);
    cudaGetSymbolAddress((void**)&hv,    g_hv);
    cudaGetSymbolAddress((void**)&ho,    g_ho);
    cudaGetSymbolAddress((void**)&h1,    g_h1);
    cudaGetSymbolAddress((void**)&h2,    g_h2);

    cudaFuncSetAttribute(flash_attn, cudaFuncAttributeMaxDynamicSharedMemorySize, FLASH_SMEM);

    auto conv = [](const float* src, __half* dst, size_t n) {
        int n4 = (int)(n / 4);
        f2h<<<(n4 + 255) / 256, 256>>>(src, dst, n4);
    };
    conv(emb_w, hemb, (size_t)D_ * IDIM);
    conv(Wq, hq, (size_t)L_ * D_ * D_);
    conv(Wk, hk, (size_t)L_ * D_ * D_);
    conv(Wv, hv, (size_t)L_ * D_ * D_);
    conv(Wo, ho, (size_t)L_ * D_ * D_);
    conv(W1, h1, (size_t)L_ * FF_ * D_);
    conv(W2, h2, (size_t)L_ * D_ * FF_);

    dim3 gProj(D_ / 64, BT / 128);       // (4, 32)
    dim3 gQKV(D_ / 64, BT / 128, 3);     // (4, 32, 3)
    dim3 gFF1(FF_ / 128, BT / 128);      // (16, 32)

    // embed: GEMM + bias -> LN(+relu, emits stats); pkn LN (fp16) upfront
    tgemm128_f<<<gProj, 256>>>(xs, hemb, emb_b, nullptr, y, D_, IDIM, 0);
    ln_pkn_all<<<dim3(NPK, L_), 64>>>(pe_k, pkn, lnk_g, lnk_b);
    ln_warp<<<BT / 8, 256>>>(y, x, emb_g, emb_bt, 1, pstat);

    for (int l = 0; l < L_; l++) {
        // QKV with ln1 fused (consumes pstat of x); v written transposed fp16
        tgemm128_qkv<<<gQKV, 256>>>(x,
            hq + (size_t)l * D_ * D_, hk + (size_t)l * D_ * D_, hv + (size_t)l * D_ * D_,
            bq + l * D_, bk + l * D_, bv + l * D_, qh, kh, vt,
            pstat, ln1_g + l * D_, ln1_b + l * D_);

        flash_attn<<<dim3(8, BH), 128, FLASH_SMEM>>>(qh, kh, vt,
            pkn + (size_t)l * NPK * DK, masks, oh);

        // Wo + residual -> x, emits stats for FF1
        tgemm128_h<<<gProj, 256>>>(oh, ho + (size_t)l * D_ * D_, bo + l * D_, x, x,
                                   D_, D_, 2, pstat);

        // FF1 with ln2 fused (consumes stats)
        tgemm256<<<gFF1, 256>>>(x, h1 + (size_t)l * FF_ * D_, b1 + l * FF_, ffh,
                                FF_, D_, 1, pstat, ln2_g + l * D_, ln2_b + l * D_);
        // FF2 + residual -> x, emits stats for next layer's QKV
        tgemm128_h<<<gProj, 256>>>(ffh, h2 + (size_t)l * D_ * FF_, b2 + l * D_, x, x,
                                   D_, FF_, 2, pstat);
    }

    ln_warp<<<BT / 8, 256>>>(x, out, after_g, after_b, 0, nullptr);
}